// round 9
// baseline (speedup 1.0000x reference)
#include <cuda_runtime.h>
#include <cstddef>

#define BSZ 512
#define TM1 31
#define DIN 256
#define HE 512
#define HD 512
#define G4 2048   // 4*HE
#define NDEC 2560 // 512 (hsW) + 2048 (lstm gates)

// ---------------- scratch (device globals; no allocation) ----------------
__device__ __align__(16) float d_t2[BSZ*TM1*DIN];       // (b, s, d)
__device__ __align__(16) float d_xh[BSZ*768];           // [w(256) | h(512)] per batch
__device__ __align__(16) float d_c_enc[BSZ*HE];
__device__ __align__(16) float d_g[BSZ*G4];             // encoder LSTM pre-activations
__device__ __align__(16) float d_enc_out[(size_t)BSZ*TM1*HE];
__device__ __align__(16) float d_encW[(size_t)BSZ*TM1*HE];
__device__ __align__(16) float d_hs[BSZ*2*HD];          // decoder [h | c]
__device__ __align__(16) float d_decbuf[BSZ*NDEC];      // [hsW(512) | gates(2048)]
__device__ __align__(16) float d_Wcat[G4*768];          // [enc_Wih | enc_Whh] row-concat
__device__ __align__(16) float d_WdecB[(size_t)NDEC*1024]; // [W1[:, :1024] ; Whh pad]
__device__ __align__(16) float d_biasEnc[G4];           // enc bih+bhh
__device__ __align__(16) float d_biasDec[NDEC];         // [0(512) | dec bih+bhh]

__device__ __forceinline__ float sigf(float x){ return 1.f/(1.f+__expf(-x)); }

__device__ __forceinline__ void mma_tf32(float* d, const unsigned* a, const unsigned* b){
  asm volatile("mma.sync.aligned.m16n8k8.row.col.f32.tf32.tf32.f32 "
    "{%0,%1,%2,%3}, {%4,%5,%6,%7}, {%8,%9}, {%0,%1,%2,%3};\n"
    : "+f"(d[0]), "+f"(d[1]), "+f"(d[2]), "+f"(d[3])
    : "r"(a[0]), "r"(a[1]), "r"(a[2]), "r"(a[3]), "r"(b[0]), "r"(b[1]));
}

// ---------------- init: build concat weights, bias sums, zero states ----------------
__global__ void init_k(const float* __restrict__ eWih, const float* __restrict__ eWhh,
                       const float* __restrict__ dW1,  const float* __restrict__ dWhh,
                       const float* __restrict__ ebih, const float* __restrict__ ebhh,
                       const float* __restrict__ dbih, const float* __restrict__ dbhh){
  int i = blockIdx.x*blockDim.x + threadIdx.x;
  if (i < G4*768){
    int n = i/768, k = i%768;
    d_Wcat[i] = (k < DIN) ? eWih[n*DIN + k] : eWhh[n*HE + (k - DIN)];
  }
  if (i < NDEC*1024){
    int n = i >> 10, k = i & 1023;
    float v;
    if (n < 512)      v = dW1[n*1536 + k];
    else if (k < 512) v = dWhh[(n-512)*512 + k];
    else              v = 0.f;
    d_WdecB[i] = v;
  }
  if (i < G4) d_biasEnc[i] = ebih[i] + ebhh[i];
  if (i < NDEC) d_biasDec[i] = (i < 512) ? 0.f : (dbih[i-512] + dbhh[i-512]);
  if (i < BSZ*HE){
    d_xh[(i/HE)*768 + DIN + (i%HE)] = 0.f;
    d_c_enc[i] = 0.f;
  }
  if (i < BSZ*2*HD) d_hs[i] = 0.f;
}

// ---------------- t2[b,s,d] = sum_t X[b,t,d]*Wd[s,t] + bd[s] ----------------
__global__ void t2_k(const float* __restrict__ inp, const float* __restrict__ Wd,
                     const float* __restrict__ bd){
  int bs = blockIdx.x;              // b*31 + s
  int b = bs / TM1, s = bs % TM1;
  int d = threadIdx.x;              // 256 threads
  __shared__ float wd[TM1];
  if (d < TM1) wd[d] = Wd[s*TM1 + d];
  __syncthreads();
  float acc = bd[s];
  const float* xb = inp + (size_t)b*TM1*257 + 1 + d;
  #pragma unroll
  for (int t = 0; t < TM1; t++) acc += xb[t*257] * wd[t];
  d_t2[(size_t)bs*DIN + d] = acc;
}

// ---- encoder fused: LSTM pointwise for step t-1 (from d_g) + attention for step t ----
__global__ void enc_fused_k(const float* __restrict__ inp, const float* __restrict__ Wc,
                            const float* __restrict__ bc, const float* __restrict__ Wa,
                            const float* __restrict__ ba, int t){
  int b = blockIdx.x, tid = threadIdx.x, lane = tid & 31, warp = tid >> 5;
  __shared__ float hsm[1024];       // [h | c]
  __shared__ float t1[TM1];
  __shared__ float red[8];
  if (t == 0){
    for (int i = tid; i < 1024; i += 256) hsm[i] = 0.f;
  } else {
    const float* g = d_g + (size_t)b*G4;
    for (int u = tid; u < HE; u += 256){
      float gi = g[u];
      float gf = g[u+512];
      float gg = g[u+1024];
      float go = g[u+1536];
      float cold = d_c_enc[b*HE + u];
      float c2 = sigf(gf)*cold + sigf(gi)*tanhf(gg);
      float h2 = sigf(go)*tanhf(c2);
      hsm[u]      = h2;
      hsm[HE + u] = c2;
      d_c_enc[b*HE + u] = c2;
      d_xh[b*768 + DIN + u] = h2;
      d_enc_out[((size_t)b*TM1 + (t-1))*HE + u] = h2;
    }
  }
  __syncthreads();
  for (int s = warp; s < TM1; s += 8){
    const float* wr = Wc + s*1024;
    float acc = 0.f;
    for (int k = lane; k < 1024; k += 32) acc += hsm[k]*wr[k];
    #pragma unroll
    for (int o = 16; o; o >>= 1) acc += __shfl_xor_sync(0xffffffffu, acc, o);
    if (!lane) t1[s] = acc + bc[s];
  }
  __syncthreads();
  float sc = ba[0];
  const float* t2p = d_t2 + (size_t)b*TM1*DIN + tid;
  #pragma unroll
  for (int s = 0; s < TM1; s++) sc += tanhf(t1[s] + t2p[s*DIN]) * Wa[s];
  float v = sc;
  #pragma unroll
  for (int o = 16; o; o >>= 1) v = fmaxf(v, __shfl_xor_sync(0xffffffffu, v, o));
  if (!lane) red[warp] = v;
  __syncthreads();
  float m = red[0];
  #pragma unroll
  for (int w = 1; w < 8; w++) m = fmaxf(m, red[w]);
  float e = __expf(sc - m);
  __syncthreads();
  v = e;
  #pragma unroll
  for (int o = 16; o; o >>= 1) v += __shfl_xor_sync(0xffffffffu, v, o);
  if (!lane) red[warp] = v;
  __syncthreads();
  float sum = 0.f;
  #pragma unroll
  for (int w = 0; w < 8; w++) sum += red[w];
  float x = inp[((size_t)b*TM1 + t)*257 + 1 + tid];
  d_xh[b*768 + tid] = (e/sum) * x;
}

// ---------------- encoder tail: pointwise for t=30 -> enc_out ----------------
__global__ void enc_tail_k(){
  int i = blockIdx.x*blockDim.x + threadIdx.x;   // B*HE
  int b = i >> 9, u = i & 511;
  const float* g = d_g + (size_t)b*G4;
  float gi = g[u];
  float gf = g[u+512];
  float gg = g[u+1024];
  float go = g[u+1536];
  float c  = d_c_enc[i];
  float c2 = sigf(gf)*c + sigf(gi)*tanhf(gg);
  float h2 = sigf(go)*tanhf(c2);
  d_enc_out[((size_t)b*TM1 + (TM1-1))*HE + u] = h2;
}

// ---------------- tf32 tensor-core GEMM, 4-stage cp.async pipeline ----------------
// C[M,N] = A[M,K] @ B[N,K]^T (+bias[n]).  M,N mult 64, K mult 32.
// 128 threads, 64x64 tile, warp = 32x32. Raw fp32 bits fed to HMMA (tf32 truncation).
// Dynamic smem: 4 stages x (As 64x36 + Bs 64x36) floats = 73728 bytes.
// Blocks with blockIdx.x >= nsplit use K2 instead of K (zero-padded B tail skip).
#define STG 4
#define STGF 2304   // 64*36 floats per operand per stage
__global__ void __launch_bounds__(128) gemm_tc(int M, int N, int K, int K2, int nsplit,
    const float* __restrict__ A, int lda,
    const float* __restrict__ B, int ldb,
    float* __restrict__ C, int ldc,
    const float* __restrict__ bias){
  extern __shared__ __align__(16) float sm[];
  float* Asm = sm;                 // [STG][64][36]
  float* Bsm = sm + STG*STGF;      // [STG][64][36]
  int tid = threadIdx.x, lane = tid & 31, warp = tid >> 5;
  int wm = warp >> 1, wn = warp & 1;
  int bm = blockIdx.y*64, bn = blockIdx.x*64;
  int Krun = (blockIdx.x < nsplit) ? K : K2;
  int KT = Krun >> 5;
  const float* Ab = A + (size_t)bm*lda;
  const float* Bb = B + (size_t)bn*ldb;
  int r0 = tid >> 3, kc = (tid & 7) << 2;

  auto issue = [&](int chunk, int s){
    float* as = Asm + s*STGF;
    float* bs = Bsm + s*STGF;
    #pragma unroll
    for (int i = 0; i < 4; i++){
      int rr = r0 + 16*i;
      unsigned da = (unsigned)__cvta_generic_to_shared(as + rr*36 + kc);
      const float* ga = Ab + (size_t)rr*lda + chunk*32 + kc;
      asm volatile("cp.async.cg.shared.global [%0], [%1], 16;\n" :: "r"(da), "l"(ga));
      unsigned db = (unsigned)__cvta_generic_to_shared(bs + rr*36 + kc);
      const float* gb = Bb + (size_t)rr*ldb + chunk*32 + kc;
      asm volatile("cp.async.cg.shared.global [%0], [%1], 16;\n" :: "r"(db), "l"(gb));
    }
    asm volatile("cp.async.commit_group;\n");
  };

  // prologue: fill 3 stages (KT >= 16 for all call sites)
  issue(0, 0); issue(1, 1); issue(2, 2);

  float acc[2][4][4] = {};
  int r = lane >> 2, c = lane & 3;

  for (int kt = 0; kt < KT; kt++){
    asm volatile("cp.async.wait_group 2;\n");   // chunk kt landed (always 3 pending)
    __syncthreads();
    if (kt + 3 < KT) issue(kt + 3, (kt + 3) & 3);
    else             asm volatile("cp.async.commit_group;\n");  // keep count at 3
    const float* as = Asm + (kt & 3)*STGF;
    const float* bs = Bsm + (kt & 3)*STGF;
    #pragma unroll
    for (int kk = 0; kk < 32; kk += 8){
      unsigned af[2][4], bf[4][2];
      #pragma unroll
      for (int mt = 0; mt < 2; mt++){
        int m0 = wm*32 + mt*16;
        af[mt][0] = __float_as_uint(as[(m0 + r    )*36 + kk + c    ]);
        af[mt][1] = __float_as_uint(as[(m0 + r + 8)*36 + kk + c    ]);
        af[mt][2] = __float_as_uint(as[(m0 + r    )*36 + kk + c + 4]);
        af[mt][3] = __float_as_uint(as[(m0 + r + 8)*36 + kk + c + 4]);
      }
      #pragma unroll
      for (int nt = 0; nt < 4; nt++){
        int n0 = wn*32 + nt*8;
        bf[nt][0] = __float_as_uint(bs[(n0 + r)*36 + kk + c    ]);
        bf[nt][1] = __float_as_uint(bs[(n0 + r)*36 + kk + c + 4]);
      }
      #pragma unroll
      for (int mt = 0; mt < 2; mt++)
        #pragma unroll
        for (int nt = 0; nt < 4; nt++)
          mma_tf32(acc[mt][nt], af[mt], bf[nt]);
    }
  }

  int c2 = (lane & 3) << 1;
  #pragma unroll
  for (int mt = 0; mt < 2; mt++){
    #pragma unroll
    for (int nt = 0; nt < 4; nt++){
      int row = bm + wm*32 + mt*16 + r;
      int col = bn + wn*32 + nt*8 + c2;
      float b0 = bias ? bias[col] : 0.f;
      float b1 = bias ? bias[col+1] : 0.f;
      float2 v0; v0.x = acc[mt][nt][0] + b0; v0.y = acc[mt][nt][1] + b1;
      float2 v1; v1.x = acc[mt][nt][2] + b0; v1.y = acc[mt][nt][3] + b1;
      *(float2*)&C[(size_t)row*ldc + col]       = v0;
      *(float2*)&C[(size_t)(row+8)*ldc + col]   = v1;
    }
  }
}

// ---------------- decoder attention + context + y_tilde + LSTM + (final) ----------
__global__ void dec_attn_k(const float* __restrict__ inp, const float* __restrict__ W2,
                           const float* __restrict__ b2, const float* __restrict__ fcW,
                           const float* __restrict__ fcb, const float* __restrict__ dWih,
                           const float* __restrict__ fcfW, const float* __restrict__ fcfb,
                           float* __restrict__ out, int t, int last){
  int b = blockIdx.x, tid = threadIdx.x, lane = tid & 31, warp = tid >> 5;
  __shared__ float sc[TM1];
  __shared__ float a_sh[TM1];
  __shared__ float red[16];
  __shared__ float s_yt, s_cd;
  const float* hw = d_decbuf + (size_t)b*NDEC;   // hsW in cols 0..511
  for (int s = warp; s < TM1; s += 8){
    const float* ew = d_encW + ((size_t)b*TM1 + s)*HE;
    float acc = 0.f;
    for (int e = lane; e < HE; e += 32) acc += tanhf(hw[e] + ew[e]) * W2[e];
    #pragma unroll
    for (int o = 16; o; o >>= 1) acc += __shfl_xor_sync(0xffffffffu, acc, o);
    if (!lane) sc[s] = acc + b2[0];
  }
  __syncthreads();
  float m = -1e30f;
  #pragma unroll
  for (int s = 0; s < TM1; s++) m = fmaxf(m, sc[s]);
  float sum = 0.f;
  #pragma unroll
  for (int s = 0; s < TM1; s++) sum += __expf(sc[s] - m);
  if (tid < TM1) a_sh[tid] = __expf(sc[tid] - m) / sum;
  __syncthreads();
  float part = 0.f, cpart = 0.f;
  for (int e = tid; e < HE; e += 256){
    const float* eo = d_enc_out + (size_t)b*TM1*HE + e;
    float acc = 0.f;
    #pragma unroll
    for (int s = 0; s < TM1; s++) acc += a_sh[s]*eo[s*HE];
    part += acc * fcW[e];
    if (last) cpart += acc * fcfW[HE + e];
  }
  #pragma unroll
  for (int o = 16; o; o >>= 1){
    part  += __shfl_xor_sync(0xffffffffu, part, o);
    cpart += __shfl_xor_sync(0xffffffffu, cpart, o);
  }
  if (!lane){ red[warp] = part; red[8+warp] = cpart; }
  __syncthreads();
  if (tid == 0){
    float tot = 0.f, ctot = 0.f;
    #pragma unroll
    for (int w = 0; w < 8; w++){ tot += red[w]; ctot += red[8+w]; }
    float yv = inp[((size_t)b*TM1 + t)*257];     // y_hist[b,t,0]
    s_yt = tot + yv*fcW[HE] + fcb[0];
    s_cd = ctot;
  }
  __syncthreads();
  float y = s_yt;
  float hpart = 0.f;
  const float* g = d_decbuf + (size_t)b*NDEC + 512;  // gates (biases included)
  for (int u = tid; u < HE; u += 256){
    float gi = g[u]      + y*dWih[u];
    float gf = g[u+512]  + y*dWih[u+512];
    float gg = g[u+1024] + y*dWih[u+1024];
    float go = g[u+1536] + y*dWih[u+1536];
    float cold = d_hs[b*1024 + 512 + u];
    float c2 = sigf(gf)*cold + sigf(gi)*tanhf(gg);
    float h2 = sigf(go)*tanhf(c2);
    d_hs[b*1024 + u]       = h2;
    d_hs[b*1024 + 512 + u] = c2;
    if (last) hpart += h2 * fcfW[u];
  }
  if (last){
    #pragma unroll
    for (int o = 16; o; o >>= 1) hpart += __shfl_xor_sync(0xffffffffu, hpart, o);
    __syncthreads();
    if (!lane) red[warp] = hpart;
    __syncthreads();
    if (tid == 0){
      float tot = 0.f;
      #pragma unroll
      for (int w = 0; w < 8; w++) tot += red[w];
      out[b] = tot + s_cd + fcfb[0];
    }
  }
}

// ---------------- launch ----------------
extern "C" void kernel_launch(void* const* d_in, const int* in_sizes, int n_in,
                              void* d_out, int out_size){
  const float* inp     = (const float*)d_in[0];
  const float* eWih    = (const float*)d_in[1];
  const float* eWhh    = (const float*)d_in[2];
  const float* ebih    = (const float*)d_in[3];
  const float* ebhh    = (const float*)d_in[4];
  const float* eWc     = (const float*)d_in[5];
  const float* ebc     = (const float*)d_in[6];
  const float* eWd     = (const float*)d_in[7];
  const float* ebd     = (const float*)d_in[8];
  const float* eWa     = (const float*)d_in[9];
  const float* eba     = (const float*)d_in[10];
  const float* dW1     = (const float*)d_in[11];
  const float* db1     = (const float*)d_in[12];
  const float* dW2     = (const float*)d_in[13];
  const float* db2     = (const float*)d_in[14];
  const float* dWih    = (const float*)d_in[15];
  const float* dWhh    = (const float*)d_in[16];
  const float* dbih    = (const float*)d_in[17];
  const float* dbhh    = (const float*)d_in[18];
  const float* fcW     = (const float*)d_in[19];
  const float* fcb     = (const float*)d_in[20];
  const float* fcfW    = (const float*)d_in[21];
  const float* fcfb    = (const float*)d_in[22];
  float* out = (float*)d_out;

  float *p_xh, *p_g, *p_Wcat, *p_enc_out, *p_encW, *p_hs, *p_decbuf, *p_WdecB, *p_bE, *p_bD;
  cudaGetSymbolAddress((void**)&p_xh, d_xh);
  cudaGetSymbolAddress((void**)&p_g, d_g);
  cudaGetSymbolAddress((void**)&p_Wcat, d_Wcat);
  cudaGetSymbolAddress((void**)&p_enc_out, d_enc_out);
  cudaGetSymbolAddress((void**)&p_encW, d_encW);
  cudaGetSymbolAddress((void**)&p_hs, d_hs);
  cudaGetSymbolAddress((void**)&p_decbuf, d_decbuf);
  cudaGetSymbolAddress((void**)&p_WdecB, d_WdecB);
  cudaGetSymbolAddress((void**)&p_bE, d_biasEnc);
  cudaGetSymbolAddress((void**)&p_bD, d_biasDec);

  const int SMEM = STG*STGF*2*sizeof(float);   // 73728 bytes
  cudaFuncSetAttribute(gemm_tc, cudaFuncAttributeMaxDynamicSharedMemorySize, SMEM);

  init_k<<<(NDEC*1024 + 255)/256, 256>>>(eWih, eWhh, dW1, dWhh, ebih, ebhh, dbih, dbhh);
  t2_k<<<BSZ*TM1, 256>>>(inp, eWd, ebd);

  dim3 gEnc(G4/64, BSZ/64);              // 32 x 8 = 256 blocks
  dim3 gEncW(HE/64, (BSZ*TM1)/64);       // 8 x 248
  dim3 gDec(NDEC/64, BSZ/64);            // 40 x 8 = 320 blocks

  // -------- encoder scan: 2 kernels per step --------
  for (int t = 0; t < TM1; t++){
    enc_fused_k<<<BSZ, 256>>>(inp, eWc, ebc, eWa, eba, t);
    gemm_tc<<<gEnc, 128, SMEM>>>(BSZ, G4, 768, 768, 9999,
                                 p_xh, 768, p_Wcat, 768, p_g, G4, p_bE);
  }
  enc_tail_k<<<BSZ*HE/256, 256>>>();

  // -------- hoisted: encW = enc_out @ W1[:,1024:].T + b1 --------
  gemm_tc<<<gEncW, 128, SMEM>>>(BSZ*TM1, HE, HE, HE, 9999,
                                p_enc_out, HE, dW1 + 1024, 1536, p_encW, HE, db1);

  // -------- decoder scan: 2 kernels per step --------
  for (int t = 0; t < TM1; t++){
    gemm_tc<<<gDec, 128, SMEM>>>(BSZ, NDEC, 1024, 512, 8,
                                 p_hs, 1024, p_WdecB, 1024, p_decbuf, NDEC, p_bD);
    dec_attn_k<<<BSZ, 256>>>(inp, dW2, db2, fcW, fcb, dWih, fcfW, fcfb,
                             out, t, t == TM1-1);
  }
}

// round 11
// speedup vs baseline: 1.4017x; 1.4017x over previous
#include <cuda_runtime.h>
#include <cstddef>

#define BSZ 512
#define TM1 31
#define DIN 256
#define HE 512
#define HD 512
#define G4 2048   // 4*HE
#define NDEC 2560 // 512 (hsW) + 2048 (lstm gates)

// ---------------- scratch (device globals; no allocation) ----------------
__device__ __align__(16) float d_t2[BSZ*TM1*DIN];       // (b, s, d)
__device__ __align__(16) float d_xh[BSZ*768];           // [w(256) | h(512)] per batch
__device__ __align__(16) float d_c_enc[BSZ*HE];
__device__ __align__(16) float d_g[BSZ*G4];             // encoder LSTM pre-activations
__device__ __align__(16) float d_enc_out[(size_t)BSZ*TM1*HE];
__device__ __align__(16) float d_encW[(size_t)BSZ*TM1*HE];
__device__ __align__(16) float d_hs[BSZ*2*HD];          // decoder [h | c]
__device__ __align__(16) float d_decbuf[BSZ*NDEC];      // [hsW(512) | gates(2048)]
__device__ __align__(16) float d_Wcat[G4*768];          // [enc_Wih | enc_Whh] row-concat
__device__ __align__(16) float d_WdecB[(size_t)NDEC*1024]; // [W1[:, :1024] ; Whh pad]
__device__ __align__(16) float d_biasEnc[G4];           // enc bih+bhh
__device__ __align__(16) float d_biasDec[NDEC];         // [0(512) | dec bih+bhh]

__device__ __forceinline__ float sigf(float x){ return 1.f/(1.f+__expf(-x)); }

__device__ __forceinline__ void mma_tf32(float* d, const unsigned* a, const unsigned* b){
  asm volatile("mma.sync.aligned.m16n8k8.row.col.f32.tf32.tf32.f32 "
    "{%0,%1,%2,%3}, {%4,%5,%6,%7}, {%8,%9}, {%0,%1,%2,%3};\n"
    : "+f"(d[0]), "+f"(d[1]), "+f"(d[2]), "+f"(d[3])
    : "r"(a[0]), "r"(a[1]), "r"(a[2]), "r"(a[3]), "r"(b[0]), "r"(b[1]));
}

// ---------------- init: build concat weights, bias sums, zero states ----------------
__global__ void init_k(const float* __restrict__ eWih, const float* __restrict__ eWhh,
                       const float* __restrict__ dW1,  const float* __restrict__ dWhh,
                       const float* __restrict__ ebih, const float* __restrict__ ebhh,
                       const float* __restrict__ dbih, const float* __restrict__ dbhh){
  int i = blockIdx.x*blockDim.x + threadIdx.x;
  if (i < G4*768){
    int n = i/768, k = i%768;
    d_Wcat[i] = (k < DIN) ? eWih[n*DIN + k] : eWhh[n*HE + (k - DIN)];
  }
  if (i < NDEC*1024){
    int n = i >> 10, k = i & 1023;
    float v;
    if (n < 512)      v = dW1[n*1536 + k];
    else if (k < 512) v = dWhh[(n-512)*512 + k];
    else              v = 0.f;
    d_WdecB[i] = v;
  }
  if (i < G4) d_biasEnc[i] = ebih[i] + ebhh[i];
  if (i < NDEC) d_biasDec[i] = (i < 512) ? 0.f : (dbih[i-512] + dbhh[i-512]);
  if (i < BSZ*HE){
    d_xh[(i/HE)*768 + DIN + (i%HE)] = 0.f;
    d_c_enc[i] = 0.f;
  }
  if (i < BSZ*2*HD) d_hs[i] = 0.f;
}

// ---------------- t2[b,s,d] = sum_t X[b,t,d]*Wd[s,t] + bd[s] ----------------
__global__ void t2_k(const float* __restrict__ inp, const float* __restrict__ Wd,
                     const float* __restrict__ bd){
  int bs = blockIdx.x;              // b*31 + s
  int b = bs / TM1, s = bs % TM1;
  int d = threadIdx.x;              // 256 threads
  __shared__ float wd[TM1];
  if (d < TM1) wd[d] = Wd[s*TM1 + d];
  __syncthreads();
  float acc = bd[s];
  const float* xb = inp + (size_t)b*TM1*257 + 1 + d;
  #pragma unroll
  for (int t = 0; t < TM1; t++) acc += xb[t*257] * wd[t];
  d_t2[(size_t)bs*DIN + d] = acc;
}

// ---- encoder fused: LSTM pointwise for step t-1 (from d_g) + attention for step t ----
__global__ void enc_fused_k(const float* __restrict__ inp, const float* __restrict__ Wc,
                            const float* __restrict__ bc, const float* __restrict__ Wa,
                            const float* __restrict__ ba, int t){
  int b = blockIdx.x, tid = threadIdx.x, lane = tid & 31, warp = tid >> 5;
  __shared__ float hsm[1024];       // [h | c]
  __shared__ float t1[TM1];
  __shared__ float red[8];
  if (t == 0){
    for (int i = tid; i < 1024; i += 256) hsm[i] = 0.f;
  } else {
    const float* g = d_g + (size_t)b*G4;
    for (int u = tid; u < HE; u += 256){
      float gi = g[u];
      float gf = g[u+512];
      float gg = g[u+1024];
      float go = g[u+1536];
      float cold = d_c_enc[b*HE + u];
      float c2 = sigf(gf)*cold + sigf(gi)*tanhf(gg);
      float h2 = sigf(go)*tanhf(c2);
      hsm[u]      = h2;
      hsm[HE + u] = c2;
      d_c_enc[b*HE + u] = c2;
      d_xh[b*768 + DIN + u] = h2;
      d_enc_out[((size_t)b*TM1 + (t-1))*HE + u] = h2;
    }
  }
  __syncthreads();
  for (int s = warp; s < TM1; s += 8){
    const float* wr = Wc + s*1024;
    float acc = 0.f;
    for (int k = lane; k < 1024; k += 32) acc += hsm[k]*wr[k];
    #pragma unroll
    for (int o = 16; o; o >>= 1) acc += __shfl_xor_sync(0xffffffffu, acc, o);
    if (!lane) t1[s] = acc + bc[s];
  }
  __syncthreads();
  float sc = ba[0];
  const float* t2p = d_t2 + (size_t)b*TM1*DIN + tid;
  #pragma unroll
  for (int s = 0; s < TM1; s++) sc += tanhf(t1[s] + t2p[s*DIN]) * Wa[s];
  float v = sc;
  #pragma unroll
  for (int o = 16; o; o >>= 1) v = fmaxf(v, __shfl_xor_sync(0xffffffffu, v, o));
  if (!lane) red[warp] = v;
  __syncthreads();
  float m = red[0];
  #pragma unroll
  for (int w = 1; w < 8; w++) m = fmaxf(m, red[w]);
  float e = __expf(sc - m);
  __syncthreads();
  v = e;
  #pragma unroll
  for (int o = 16; o; o >>= 1) v += __shfl_xor_sync(0xffffffffu, v, o);
  if (!lane) red[warp] = v;
  __syncthreads();
  float sum = 0.f;
  #pragma unroll
  for (int w = 0; w < 8; w++) sum += red[w];
  float x = inp[((size_t)b*TM1 + t)*257 + 1 + tid];
  d_xh[b*768 + tid] = (e/sum) * x;
}

// ---------------- encoder tail: pointwise for t=30 -> enc_out ----------------
__global__ void enc_tail_k(){
  int i = blockIdx.x*blockDim.x + threadIdx.x;   // B*HE
  int b = i >> 9, u = i & 511;
  const float* g = d_g + (size_t)b*G4;
  float gi = g[u];
  float gf = g[u+512];
  float gg = g[u+1024];
  float go = g[u+1536];
  float c  = d_c_enc[i];
  float c2 = sigf(gf)*c + sigf(gi)*tanhf(gg);
  float h2 = sigf(go)*tanhf(c2);
  d_enc_out[((size_t)b*TM1 + (TM1-1))*HE + u] = h2;
}

// ---------------- tf32 tensor-core GEMM: 32(M)x64(N) tile, 128 threads ----------
// C[M,N] = A[M,K] @ B[N,K]^T (+bias[n]).  M mult 32, N mult 64, K mult 32.
// 4 warps, warp-tile 16x32. Register-prefetch double buffer (R4-proven loop).
// Raw fp32 bits fed to HMMA (tf32 truncation, no cvt).
// Blocks with blockIdx.x >= nsplit use K2 instead of K (zero-padded B tail skip).
#define GK 32
__global__ void __launch_bounds__(128) gemm_tc(int M, int N, int K, int K2, int nsplit,
    const float* __restrict__ A, int lda,
    const float* __restrict__ B, int ldb,
    float* __restrict__ C, int ldc,
    const float* __restrict__ bias){
  __shared__ __align__(16) float As[32][GK+4];   // stride 36
  __shared__ __align__(16) float Bs[64][GK+4];
  int tid = threadIdx.x, lane = tid & 31, warp = tid >> 5;
  int wm = warp >> 1, wn = warp & 1;             // 2 x 2 warp grid, 16x32 each
  int bm = blockIdx.y*32, bn = blockIdx.x*64;
  int Krun = (blockIdx.x < nsplit) ? K : K2;
  const float* Ab = A + (size_t)bm*lda;
  const float* Bb = B + (size_t)bn*ldb;
  int r0 = tid >> 3, kc = (tid & 7) << 2;        // A: rows 0..15 (+16), B: rows 0..15 (+16,32,48)

  float4 ar[2], br[4];
  #pragma unroll
  for (int i = 0; i < 2; i++)
    ar[i] = *(const float4*)(Ab + (size_t)(r0 + 16*i)*lda + kc);
  #pragma unroll
  for (int i = 0; i < 4; i++)
    br[i] = *(const float4*)(Bb + (size_t)(r0 + 16*i)*ldb + kc);

  float acc[4][4] = {};
  int r = lane >> 2, c = lane & 3;

  for (int k0 = 0; k0 < Krun; k0 += GK){
    #pragma unroll
    for (int i = 0; i < 2; i++)
      *(float4*)&As[r0 + 16*i][kc] = ar[i];
    #pragma unroll
    for (int i = 0; i < 4; i++)
      *(float4*)&Bs[r0 + 16*i][kc] = br[i];
    __syncthreads();
    if (k0 + GK < Krun){
      #pragma unroll
      for (int i = 0; i < 2; i++)
        ar[i] = *(const float4*)(Ab + (size_t)(r0 + 16*i)*lda + k0 + GK + kc);
      #pragma unroll
      for (int i = 0; i < 4; i++)
        br[i] = *(const float4*)(Bb + (size_t)(r0 + 16*i)*ldb + k0 + GK + kc);
    }
    #pragma unroll
    for (int kk = 0; kk < GK; kk += 8){
      unsigned af[4], bf[4][2];
      int m0 = wm*16;
      af[0] = __float_as_uint(As[m0 + r    ][kk + c    ]);
      af[1] = __float_as_uint(As[m0 + r + 8][kk + c    ]);
      af[2] = __float_as_uint(As[m0 + r    ][kk + c + 4]);
      af[3] = __float_as_uint(As[m0 + r + 8][kk + c + 4]);
      #pragma unroll
      for (int nt = 0; nt < 4; nt++){
        int n0 = wn*32 + nt*8;
        bf[nt][0] = __float_as_uint(Bs[n0 + r][kk + c    ]);
        bf[nt][1] = __float_as_uint(Bs[n0 + r][kk + c + 4]);
      }
      #pragma unroll
      for (int nt = 0; nt < 4; nt++)
        mma_tf32(acc[nt], af, bf[nt]);
    }
    __syncthreads();
  }

  int c2 = (lane & 3) << 1;
  #pragma unroll
  for (int nt = 0; nt < 4; nt++){
    int row = bm + wm*16 + r;
    int col = bn + wn*32 + nt*8 + c2;
    float b0 = bias ? bias[col] : 0.f;
    float b1 = bias ? bias[col+1] : 0.f;
    float2 v0; v0.x = acc[nt][0] + b0; v0.y = acc[nt][1] + b1;
    float2 v1; v1.x = acc[nt][2] + b0; v1.y = acc[nt][3] + b1;
    *(float2*)&C[(size_t)row*ldc + col]       = v0;
    *(float2*)&C[(size_t)(row+8)*ldc + col]   = v1;
  }
}

// ---------------- decoder attention + context + y_tilde + LSTM + (final) ----------
__global__ void dec_attn_k(const float* __restrict__ inp, const float* __restrict__ W2,
                           const float* __restrict__ b2, const float* __restrict__ fcW,
                           const float* __restrict__ fcb, const float* __restrict__ dWih,
                           const float* __restrict__ fcfW, const float* __restrict__ fcfb,
                           float* __restrict__ out, int t, int last){
  int b = blockIdx.x, tid = threadIdx.x, lane = tid & 31, warp = tid >> 5;
  __shared__ float sc[TM1];
  __shared__ float a_sh[TM1];
  __shared__ float red[16];
  __shared__ float s_yt, s_cd;
  const float* hw = d_decbuf + (size_t)b*NDEC;   // hsW in cols 0..511
  for (int s = warp; s < TM1; s += 8){
    const float* ew = d_encW + ((size_t)b*TM1 + s)*HE;
    float acc = 0.f;
    for (int e = lane; e < HE; e += 32) acc += tanhf(hw[e] + ew[e]) * W2[e];
    #pragma unroll
    for (int o = 16; o; o >>= 1) acc += __shfl_xor_sync(0xffffffffu, acc, o);
    if (!lane) sc[s] = acc + b2[0];
  }
  __syncthreads();
  float m = -1e30f;
  #pragma unroll
  for (int s = 0; s < TM1; s++) m = fmaxf(m, sc[s]);
  float sum = 0.f;
  #pragma unroll
  for (int s = 0; s < TM1; s++) sum += __expf(sc[s] - m);
  if (tid < TM1) a_sh[tid] = __expf(sc[tid] - m) / sum;
  __syncthreads();
  float part = 0.f, cpart = 0.f;
  for (int e = tid; e < HE; e += 256){
    const float* eo = d_enc_out + (size_t)b*TM1*HE + e;
    float acc = 0.f;
    #pragma unroll
    for (int s = 0; s < TM1; s++) acc += a_sh[s]*eo[s*HE];
    part += acc * fcW[e];
    if (last) cpart += acc * fcfW[HE + e];
  }
  #pragma unroll
  for (int o = 16; o; o >>= 1){
    part  += __shfl_xor_sync(0xffffffffu, part, o);
    cpart += __shfl_xor_sync(0xffffffffu, cpart, o);
  }
  if (!lane){ red[warp] = part; red[8+warp] = cpart; }
  __syncthreads();
  if (tid == 0){
    float tot = 0.f, ctot = 0.f;
    #pragma unroll
    for (int w = 0; w < 8; w++){ tot += red[w]; ctot += red[8+w]; }
    float yv = inp[((size_t)b*TM1 + t)*257];     // y_hist[b,t,0]
    s_yt = tot + yv*fcW[HE] + fcb[0];
    s_cd = ctot;
  }
  __syncthreads();
  float y = s_yt;
  float hpart = 0.f;
  const float* g = d_decbuf + (size_t)b*NDEC + 512;  // gates (biases included)
  for (int u = tid; u < HE; u += 256){
    float gi = g[u]      + y*dWih[u];
    float gf = g[u+512]  + y*dWih[u+512];
    float gg = g[u+1024] + y*dWih[u+1024];
    float go = g[u+1536] + y*dWih[u+1536];
    float cold = d_hs[b*1024 + 512 + u];
    float c2 = sigf(gf)*cold + sigf(gi)*tanhf(gg);
    float h2 = sigf(go)*tanhf(c2);
    d_hs[b*1024 + u]       = h2;
    d_hs[b*1024 + 512 + u] = c2;
    if (last) hpart += h2 * fcfW[u];
  }
  if (last){
    #pragma unroll
    for (int o = 16; o; o >>= 1) hpart += __shfl_xor_sync(0xffffffffu, hpart, o);
    __syncthreads();
    if (!lane) red[warp] = hpart;
    __syncthreads();
    if (tid == 0){
      float tot = 0.f;
      #pragma unroll
      for (int w = 0; w < 8; w++) tot += red[w];
      out[b] = tot + s_cd + fcfb[0];
    }
  }
}

// ---------------- launch ----------------
extern "C" void kernel_launch(void* const* d_in, const int* in_sizes, int n_in,
                              void* d_out, int out_size){
  const float* inp     = (const float*)d_in[0];
  const float* eWih    = (const float*)d_in[1];
  const float* eWhh    = (const float*)d_in[2];
  const float* ebih    = (const float*)d_in[3];
  const float* ebhh    = (const float*)d_in[4];
  const float* eWc     = (const float*)d_in[5];
  const float* ebc     = (const float*)d_in[6];
  const float* eWd     = (const float*)d_in[7];
  const float* ebd     = (const float*)d_in[8];
  const float* eWa     = (const float*)d_in[9];
  const float* eba     = (const float*)d_in[10];
  const float* dW1     = (const float*)d_in[11];
  const float* db1     = (const float*)d_in[12];
  const float* dW2     = (const float*)d_in[13];
  const float* db2     = (const float*)d_in[14];
  const float* dWih    = (const float*)d_in[15];
  const float* dWhh    = (const float*)d_in[16];
  const float* dbih    = (const float*)d_in[17];
  const float* dbhh    = (const float*)d_in[18];
  const float* fcW     = (const float*)d_in[19];
  const float* fcb     = (const float*)d_in[20];
  const float* fcfW    = (const float*)d_in[21];
  const float* fcfb    = (const float*)d_in[22];
  float* out = (float*)d_out;

  float *p_xh, *p_g, *p_Wcat, *p_enc_out, *p_encW, *p_hs, *p_decbuf, *p_WdecB, *p_bE, *p_bD;
  cudaGetSymbolAddress((void**)&p_xh, d_xh);
  cudaGetSymbolAddress((void**)&p_g, d_g);
  cudaGetSymbolAddress((void**)&p_Wcat, d_Wcat);
  cudaGetSymbolAddress((void**)&p_enc_out, d_enc_out);
  cudaGetSymbolAddress((void**)&p_encW, d_encW);
  cudaGetSymbolAddress((void**)&p_hs, d_hs);
  cudaGetSymbolAddress((void**)&p_decbuf, d_decbuf);
  cudaGetSymbolAddress((void**)&p_WdecB, d_WdecB);
  cudaGetSymbolAddress((void**)&p_bE, d_biasEnc);
  cudaGetSymbolAddress((void**)&p_bD, d_biasDec);

  init_k<<<(NDEC*1024 + 255)/256, 256>>>(eWih, eWhh, dW1, dWhh, ebih, ebhh, dbih, dbhh);
  t2_k<<<BSZ*TM1, 256>>>(inp, eWd, ebd);

  dim3 gEnc(G4/64, BSZ/32);              // 32 x 16 = 512 blocks
  dim3 gEncW(HE/64, (BSZ*TM1)/32);       // 8 x 496 = 3968 blocks
  dim3 gDec(NDEC/64, BSZ/32);            // 40 x 16 = 640 blocks

  // -------- encoder scan: 2 kernels per step --------
  for (int t = 0; t < TM1; t++){
    enc_fused_k<<<BSZ, 256>>>(inp, eWc, ebc, eWa, eba, t);
    gemm_tc<<<gEnc, 128>>>(BSZ, G4, 768, 768, 9999,
                           p_xh, 768, p_Wcat, 768, p_g, G4, p_bE);
  }
  enc_tail_k<<<BSZ*HE/256, 256>>>();

  // -------- hoisted: encW = enc_out @ W1[:,1024:].T + b1 --------
  gemm_tc<<<gEncW, 128>>>(BSZ*TM1, HE, HE, HE, 9999,
                          p_enc_out, HE, dW1 + 1024, 1536, p_encW, HE, db1);

  // -------- decoder scan: 2 kernels per step --------
  for (int t = 0; t < TM1; t++){
    gemm_tc<<<gDec, 128>>>(BSZ, NDEC, 1024, 512, 8,
                           p_hs, 1024, p_WdecB, 1024, p_decbuf, NDEC, p_bD);
    dec_attn_k<<<BSZ, 256>>>(inp, dW2, db2, fcW, fcb, dWih, fcfW, fcfb,
                             out, t, t == TM1-1);
  }
}

// round 12
// speedup vs baseline: 1.6218x; 1.1570x over previous
#include <cuda_runtime.h>
#include <cstddef>

#define BSZ 512
#define TM1 31
#define DIN 256
#define HE 512
#define HD 512
#define G4 2048   // 4*HE
#define NDEC 2560 // 512 (hsW) + 2048 (lstm gates)

// ---------------- scratch (device globals; no allocation) ----------------
__device__ __align__(16) float d_t2[BSZ*TM1*DIN];       // (b, s, d)
__device__ __align__(16) float d_xh[BSZ*768];           // [w(256) | h(512)] per batch
__device__ __align__(16) float d_c_enc[BSZ*HE];
__device__ __align__(16) float d_g[BSZ*G4];             // encoder LSTM pre-activations
__device__ __align__(16) float d_enc_out[(size_t)BSZ*TM1*HE];
__device__ __align__(16) float d_encW[(size_t)BSZ*TM1*HE];
__device__ __align__(16) float d_hs[BSZ*2*HD];          // decoder [h | c]
__device__ __align__(16) float d_decbuf[BSZ*NDEC];      // [hsW(512) | gates(2048)]
__device__ __align__(16) float d_Wcat[G4*768];          // [enc_Wih | enc_Whh] row-concat
__device__ __align__(16) float d_WdecB[(size_t)NDEC*1024]; // [W1[:, :1024] ; Whh pad]
__device__ __align__(16) float d_biasEnc[G4];           // enc bih+bhh
__device__ __align__(16) float d_biasDec[NDEC];         // [0(512) | dec bih+bhh]

__device__ __forceinline__ float sigf(float x){ return 1.f/(1.f+__expf(-x)); }

__device__ __forceinline__ void mma_tf32(float* d, const unsigned* a, const unsigned* b){
  asm volatile("mma.sync.aligned.m16n8k8.row.col.f32.tf32.tf32.f32 "
    "{%0,%1,%2,%3}, {%4,%5,%6,%7}, {%8,%9}, {%0,%1,%2,%3};\n"
    : "+f"(d[0]), "+f"(d[1]), "+f"(d[2]), "+f"(d[3])
    : "r"(a[0]), "r"(a[1]), "r"(a[2]), "r"(a[3]), "r"(b[0]), "r"(b[1]));
}

// ---------------- init: build concat weights, bias sums, zero states ----------------
__global__ void init_k(const float* __restrict__ eWih, const float* __restrict__ eWhh,
                       const float* __restrict__ dW1,  const float* __restrict__ dWhh,
                       const float* __restrict__ ebih, const float* __restrict__ ebhh,
                       const float* __restrict__ dbih, const float* __restrict__ dbhh){
  int i = blockIdx.x*blockDim.x + threadIdx.x;
  if (i < G4*768){
    int n = i/768, k = i%768;
    d_Wcat[i] = (k < DIN) ? eWih[n*DIN + k] : eWhh[n*HE + (k - DIN)];
  }
  if (i < NDEC*1024){
    int n = i >> 10, k = i & 1023;
    float v;
    if (n < 512)      v = dW1[n*1536 + k];
    else if (k < 512) v = dWhh[(n-512)*512 + k];
    else              v = 0.f;
    d_WdecB[i] = v;
  }
  if (i < G4) d_biasEnc[i] = ebih[i] + ebhh[i];
  if (i < NDEC) d_biasDec[i] = (i < 512) ? 0.f : (dbih[i-512] + dbhh[i-512]);
  if (i < BSZ*HE){
    d_xh[(i/HE)*768 + DIN + (i%HE)] = 0.f;
    d_c_enc[i] = 0.f;
  }
  if (i < BSZ*2*HD) d_hs[i] = 0.f;
}

// ---------------- t2[b,s,d] = sum_t X[b,t,d]*Wd[s,t] + bd[s] ----------------
__global__ void t2_k(const float* __restrict__ inp, const float* __restrict__ Wd,
                     const float* __restrict__ bd){
  int bs = blockIdx.x;              // b*31 + s
  int b = bs / TM1, s = bs % TM1;
  int d = threadIdx.x;              // 256 threads
  __shared__ float wd[TM1];
  if (d < TM1) wd[d] = Wd[s*TM1 + d];
  __syncthreads();
  float acc = bd[s];
  const float* xb = inp + (size_t)b*TM1*257 + 1 + d;
  #pragma unroll
  for (int t = 0; t < TM1; t++) acc += xb[t*257] * wd[t];
  d_t2[(size_t)bs*DIN + d] = acc;
}

// ---- encoder fused: LSTM pointwise for step t-1 (from d_g) + attention for step t ----
__global__ void enc_fused_k(const float* __restrict__ inp, const float* __restrict__ Wc,
                            const float* __restrict__ bc, const float* __restrict__ Wa,
                            const float* __restrict__ ba, int t){
  int b = blockIdx.x, tid = threadIdx.x, lane = tid & 31, warp = tid >> 5;
  __shared__ float hsm[1024];       // [h | c]
  __shared__ float t1[TM1];
  __shared__ float red[8];
  if (t == 0){
    for (int i = tid; i < 1024; i += 256) hsm[i] = 0.f;
  } else {
    const float* g = d_g + (size_t)b*G4;
    for (int u = tid; u < HE; u += 256){
      float gi = g[u];
      float gf = g[u+512];
      float gg = g[u+1024];
      float go = g[u+1536];
      float cold = d_c_enc[b*HE + u];
      float c2 = sigf(gf)*cold + sigf(gi)*tanhf(gg);
      float h2 = sigf(go)*tanhf(c2);
      hsm[u]      = h2;
      hsm[HE + u] = c2;
      d_c_enc[b*HE + u] = c2;
      d_xh[b*768 + DIN + u] = h2;
      d_enc_out[((size_t)b*TM1 + (t-1))*HE + u] = h2;
    }
  }
  __syncthreads();
  for (int s = warp; s < TM1; s += 8){
    const float* wr = Wc + s*1024;
    float acc = 0.f;
    for (int k = lane; k < 1024; k += 32) acc += hsm[k]*wr[k];
    #pragma unroll
    for (int o = 16; o; o >>= 1) acc += __shfl_xor_sync(0xffffffffu, acc, o);
    if (!lane) t1[s] = acc + bc[s];
  }
  __syncthreads();
  float sc = ba[0];
  const float* t2p = d_t2 + (size_t)b*TM1*DIN + tid;
  #pragma unroll
  for (int s = 0; s < TM1; s++) sc += tanhf(t1[s] + t2p[s*DIN]) * Wa[s];
  float v = sc;
  #pragma unroll
  for (int o = 16; o; o >>= 1) v = fmaxf(v, __shfl_xor_sync(0xffffffffu, v, o));
  if (!lane) red[warp] = v;
  __syncthreads();
  float m = red[0];
  #pragma unroll
  for (int w = 1; w < 8; w++) m = fmaxf(m, red[w]);
  float e = __expf(sc - m);
  __syncthreads();
  v = e;
  #pragma unroll
  for (int o = 16; o; o >>= 1) v += __shfl_xor_sync(0xffffffffu, v, o);
  if (!lane) red[warp] = v;
  __syncthreads();
  float sum = 0.f;
  #pragma unroll
  for (int w = 0; w < 8; w++) sum += red[w];
  float x = inp[((size_t)b*TM1 + t)*257 + 1 + tid];
  d_xh[b*768 + tid] = (e/sum) * x;
}

// ---------------- encoder tail: pointwise for t=30 -> enc_out ----------------
__global__ void enc_tail_k(){
  int i = blockIdx.x*blockDim.x + threadIdx.x;   // B*HE
  int b = i >> 9, u = i & 511;
  const float* g = d_g + (size_t)b*G4;
  float gi = g[u];
  float gf = g[u+512];
  float gg = g[u+1024];
  float go = g[u+1536];
  float c  = d_c_enc[i];
  float c2 = sigf(gf)*c + sigf(gi)*tanhf(gg);
  float h2 = sigf(go)*tanhf(c2);
  d_enc_out[((size_t)b*TM1 + (TM1-1))*HE + u] = h2;
}

// ---------------- tf32 tensor-core GEMM: 64x64 tile, 128 threads -----------------
// C[M,N] = A[M,K] @ B[N,K]^T (+bias[n]).  M,N mult 64, K mult 32.
// Register-prefetch + double-buffered smem: ONE __syncthreads per K-chunk.
// Raw fp32 bits fed to HMMA (tf32 truncation, no cvt).
// Blocks with blockIdx.x >= nsplit use K2 instead of K (zero-padded B tail skip).
#define GK 32
__global__ void __launch_bounds__(128) gemm_tc(int M, int N, int K, int K2, int nsplit,
    const float* __restrict__ A, int lda,
    const float* __restrict__ B, int ldb,
    float* __restrict__ C, int ldc,
    const float* __restrict__ bias){
  __shared__ __align__(16) float As[2][64][GK+4];   // stride 36, 2 stages
  __shared__ __align__(16) float Bs[2][64][GK+4];
  int tid = threadIdx.x, lane = tid & 31, warp = tid >> 5;
  int wm = warp >> 1, wn = warp & 1;
  int bm = blockIdx.y*64, bn = blockIdx.x*64;
  int Krun = (blockIdx.x < nsplit) ? K : K2;
  int KT = Krun >> 5;
  const float* Ab = A + (size_t)bm*lda;
  const float* Bb = B + (size_t)bn*ldb;
  int r0 = tid >> 3, kc = (tid & 7) << 2;

  float4 ar[4], br[4];
  #pragma unroll
  for (int i = 0; i < 4; i++){
    int row = r0 + 16*i;
    ar[i] = *(const float4*)(Ab + (size_t)row*lda + kc);
    br[i] = *(const float4*)(Bb + (size_t)row*ldb + kc);
  }
  #pragma unroll
  for (int i = 0; i < 4; i++){
    int row = r0 + 16*i;
    *(float4*)&As[0][row][kc] = ar[i];
    *(float4*)&Bs[0][row][kc] = br[i];
  }
  __syncthreads();

  float acc[2][4][4] = {};
  int r = lane >> 2, c = lane & 3;

  for (int kt = 0; kt < KT; kt++){
    int cur = kt & 1;
    // prefetch next chunk into registers (overlaps with MMAs below)
    if (kt + 1 < KT){
      #pragma unroll
      for (int i = 0; i < 4; i++){
        int row = r0 + 16*i;
        ar[i] = *(const float4*)(Ab + (size_t)row*lda + (kt+1)*GK + kc);
        br[i] = *(const float4*)(Bb + (size_t)row*ldb + (kt+1)*GK + kc);
      }
    }
    #pragma unroll
    for (int kk = 0; kk < GK; kk += 8){
      unsigned af[2][4], bf[4][2];
      #pragma unroll
      for (int mt = 0; mt < 2; mt++){
        int m0 = wm*32 + mt*16;
        af[mt][0] = __float_as_uint(As[cur][m0 + r    ][kk + c    ]);
        af[mt][1] = __float_as_uint(As[cur][m0 + r + 8][kk + c    ]);
        af[mt][2] = __float_as_uint(As[cur][m0 + r    ][kk + c + 4]);
        af[mt][3] = __float_as_uint(As[cur][m0 + r + 8][kk + c + 4]);
      }
      #pragma unroll
      for (int nt = 0; nt < 4; nt++){
        int n0 = wn*32 + nt*8;
        bf[nt][0] = __float_as_uint(Bs[cur][n0 + r][kk + c    ]);
        bf[nt][1] = __float_as_uint(Bs[cur][n0 + r][kk + c + 4]);
      }
      #pragma unroll
      for (int mt = 0; mt < 2; mt++)
        #pragma unroll
        for (int nt = 0; nt < 4; nt++)
          mma_tf32(acc[mt][nt], af[mt], bf[nt]);
    }
    if (kt + 1 < KT){
      int nxt = cur ^ 1;
      #pragma unroll
      for (int i = 0; i < 4; i++){
        int row = r0 + 16*i;
        *(float4*)&As[nxt][row][kc] = ar[i];
        *(float4*)&Bs[nxt][row][kc] = br[i];
      }
      __syncthreads();
    }
  }

  int c2 = (lane & 3) << 1;
  #pragma unroll
  for (int mt = 0; mt < 2; mt++){
    #pragma unroll
    for (int nt = 0; nt < 4; nt++){
      int row = bm + wm*32 + mt*16 + r;
      int col = bn + wn*32 + nt*8 + c2;
      float b0 = bias ? bias[col] : 0.f;
      float b1 = bias ? bias[col+1] : 0.f;
      float2 v0; v0.x = acc[mt][nt][0] + b0; v0.y = acc[mt][nt][1] + b1;
      float2 v1; v1.x = acc[mt][nt][2] + b0; v1.y = acc[mt][nt][3] + b1;
      *(float2*)&C[(size_t)row*ldc + col]       = v0;
      *(float2*)&C[(size_t)(row+8)*ldc + col]   = v1;
    }
  }
}

// ---------------- decoder attention + context + y_tilde + LSTM + (final) ----------
__global__ void dec_attn_k(const float* __restrict__ inp, const float* __restrict__ W2,
                           const float* __restrict__ b2, const float* __restrict__ fcW,
                           const float* __restrict__ fcb, const float* __restrict__ dWih,
                           const float* __restrict__ fcfW, const float* __restrict__ fcfb,
                           float* __restrict__ out, int t, int last){
  int b = blockIdx.x, tid = threadIdx.x, lane = tid & 31, warp = tid >> 5;
  __shared__ float sc[TM1];
  __shared__ float a_sh[TM1];
  __shared__ float red[16];
  __shared__ float s_yt, s_cd;
  const float* hw = d_decbuf + (size_t)b*NDEC;   // hsW in cols 0..511
  for (int s = warp; s < TM1; s += 8){
    const float* ew = d_encW + ((size_t)b*TM1 + s)*HE;
    float acc = 0.f;
    for (int e = lane; e < HE; e += 32) acc += tanhf(hw[e] + ew[e]) * W2[e];
    #pragma unroll
    for (int o = 16; o; o >>= 1) acc += __shfl_xor_sync(0xffffffffu, acc, o);
    if (!lane) sc[s] = acc + b2[0];
  }
  __syncthreads();
  float m = -1e30f;
  #pragma unroll
  for (int s = 0; s < TM1; s++) m = fmaxf(m, sc[s]);
  float sum = 0.f;
  #pragma unroll
  for (int s = 0; s < TM1; s++) sum += __expf(sc[s] - m);
  if (tid < TM1) a_sh[tid] = __expf(sc[tid] - m) / sum;
  __syncthreads();
  float part = 0.f, cpart = 0.f;
  for (int e = tid; e < HE; e += 256){
    const float* eo = d_enc_out + (size_t)b*TM1*HE + e;
    float acc = 0.f;
    #pragma unroll
    for (int s = 0; s < TM1; s++) acc += a_sh[s]*eo[s*HE];
    part += acc * fcW[e];
    if (last) cpart += acc * fcfW[HE + e];
  }
  #pragma unroll
  for (int o = 16; o; o >>= 1){
    part  += __shfl_xor_sync(0xffffffffu, part, o);
    cpart += __shfl_xor_sync(0xffffffffu, cpart, o);
  }
  if (!lane){ red[warp] = part; red[8+warp] = cpart; }
  __syncthreads();
  if (tid == 0){
    float tot = 0.f, ctot = 0.f;
    #pragma unroll
    for (int w = 0; w < 8; w++){ tot += red[w]; ctot += red[8+w]; }
    float yv = inp[((size_t)b*TM1 + t)*257];     // y_hist[b,t,0]
    s_yt = tot + yv*fcW[HE] + fcb[0];
    s_cd = ctot;
  }
  __syncthreads();
  float y = s_yt;
  float hpart = 0.f;
  const float* g = d_decbuf + (size_t)b*NDEC + 512;  // gates (biases included)
  for (int u = tid; u < HE; u += 256){
    float gi = g[u]      + y*dWih[u];
    float gf = g[u+512]  + y*dWih[u+512];
    float gg = g[u+1024] + y*dWih[u+1024];
    float go = g[u+1536] + y*dWih[u+1536];
    float cold = d_hs[b*1024 + 512 + u];
    float c2 = sigf(gf)*cold + sigf(gi)*tanhf(gg);
    float h2 = sigf(go)*tanhf(c2);
    d_hs[b*1024 + u]       = h2;
    d_hs[b*1024 + 512 + u] = c2;
    if (last) hpart += h2 * fcfW[u];
  }
  if (last){
    #pragma unroll
    for (int o = 16; o; o >>= 1) hpart += __shfl_xor_sync(0xffffffffu, hpart, o);
    __syncthreads();
    if (!lane) red[warp] = hpart;
    __syncthreads();
    if (tid == 0){
      float tot = 0.f;
      #pragma unroll
      for (int w = 0; w < 8; w++) tot += red[w];
      out[b] = tot + s_cd + fcfb[0];
    }
  }
}

// ---------------- launch ----------------
extern "C" void kernel_launch(void* const* d_in, const int* in_sizes, int n_in,
                              void* d_out, int out_size){
  const float* inp     = (const float*)d_in[0];
  const float* eWih    = (const float*)d_in[1];
  const float* eWhh    = (const float*)d_in[2];
  const float* ebih    = (const float*)d_in[3];
  const float* ebhh    = (const float*)d_in[4];
  const float* eWc     = (const float*)d_in[5];
  const float* ebc     = (const float*)d_in[6];
  const float* eWd     = (const float*)d_in[7];
  const float* ebd     = (const float*)d_in[8];
  const float* eWa     = (const float*)d_in[9];
  const float* eba     = (const float*)d_in[10];
  const float* dW1     = (const float*)d_in[11];
  const float* db1     = (const float*)d_in[12];
  const float* dW2     = (const float*)d_in[13];
  const float* db2     = (const float*)d_in[14];
  const float* dWih    = (const float*)d_in[15];
  const float* dWhh    = (const float*)d_in[16];
  const float* dbih    = (const float*)d_in[17];
  const float* dbhh    = (const float*)d_in[18];
  const float* fcW     = (const float*)d_in[19];
  const float* fcb     = (const float*)d_in[20];
  const float* fcfW    = (const float*)d_in[21];
  const float* fcfb    = (const float*)d_in[22];
  float* out = (float*)d_out;

  float *p_xh, *p_g, *p_Wcat, *p_enc_out, *p_encW, *p_hs, *p_decbuf, *p_WdecB, *p_bE, *p_bD;
  cudaGetSymbolAddress((void**)&p_xh, d_xh);
  cudaGetSymbolAddress((void**)&p_g, d_g);
  cudaGetSymbolAddress((void**)&p_Wcat, d_Wcat);
  cudaGetSymbolAddress((void**)&p_enc_out, d_enc_out);
  cudaGetSymbolAddress((void**)&p_encW, d_encW);
  cudaGetSymbolAddress((void**)&p_hs, d_hs);
  cudaGetSymbolAddress((void**)&p_decbuf, d_decbuf);
  cudaGetSymbolAddress((void**)&p_WdecB, d_WdecB);
  cudaGetSymbolAddress((void**)&p_bE, d_biasEnc);
  cudaGetSymbolAddress((void**)&p_bD, d_biasDec);

  init_k<<<(NDEC*1024 + 255)/256, 256>>>(eWih, eWhh, dW1, dWhh, ebih, ebhh, dbih, dbhh);
  t2_k<<<BSZ*TM1, 256>>>(inp, eWd, ebd);

  dim3 gEnc(G4/64, BSZ/64);              // 32 x 8 = 256 blocks
  dim3 gEncW(HE/64, (BSZ*TM1)/64);       // 8 x 248 = 1984 blocks
  dim3 gDec(NDEC/64, BSZ/64);            // 40 x 8 = 320 blocks

  // -------- encoder scan: 2 kernels per step --------
  for (int t = 0; t < TM1; t++){
    enc_fused_k<<<BSZ, 256>>>(inp, eWc, ebc, eWa, eba, t);
    gemm_tc<<<gEnc, 128>>>(BSZ, G4, 768, 768, 9999,
                           p_xh, 768, p_Wcat, 768, p_g, G4, p_bE);
  }
  enc_tail_k<<<BSZ*HE/256, 256>>>();

  // -------- hoisted: encW = enc_out @ W1[:,1024:].T + b1 --------
  gemm_tc<<<gEncW, 128>>>(BSZ*TM1, HE, HE, HE, 9999,
                          p_enc_out, HE, dW1 + 1024, 1536, p_encW, HE, db1);

  // -------- decoder scan: 2 kernels per step --------
  for (int t = 0; t < TM1; t++){
    gemm_tc<<<gDec, 128>>>(BSZ, NDEC, 1024, 512, 8,
                           p_hs, 1024, p_WdecB, 1024, p_decbuf, NDEC, p_bD);
    dec_attn_k<<<BSZ, 256>>>(inp, dW2, db2, fcW, fcb, dWih, fcfW, fcfb,
                             out, t, t == TM1-1);
  }
}

// round 13
// speedup vs baseline: 1.8346x; 1.1312x over previous
#include <cuda_runtime.h>
#include <cstddef>

#define BSZ 512
#define TM1 31
#define DIN 256
#define HE 512
#define HD 512
#define G4 2048   // 4*HE
#define NDEC 2560 // 512 (hsW) + 2048 (lstm gates)

// ---------------- scratch (device globals; no allocation) ----------------
__device__ __align__(16) float d_t2[BSZ*TM1*DIN];       // (b, s, d)
__device__ __align__(16) float d_xh[BSZ*768];           // [w(256) | h(512)] per batch
__device__ __align__(16) float d_c_enc[BSZ*HE];
__device__ __align__(16) float d_gs[2*BSZ*G4];          // enc gates, split-K halves
__device__ __align__(16) float d_enc_out[(size_t)BSZ*TM1*HE];
__device__ __align__(16) float d_encW[(size_t)BSZ*TM1*HE];
__device__ __align__(16) float d_hs[BSZ*2*HD];          // decoder [h | c]
__device__ __align__(16) float d_db[2*BSZ*NDEC];        // dec [hsW|gates], split-K halves
__device__ __align__(16) float d_Wcat[G4*768];          // [enc_Wih | enc_Whh] row-concat
__device__ __align__(16) float d_WdecB[(size_t)NDEC*1024]; // [W1[:, :1024] ; Whh pad]
__device__ __align__(16) float d_biasEnc[G4];           // enc bih+bhh
__device__ __align__(16) float d_biasDec[NDEC];         // [0(512) | dec bih+bhh]

__device__ __forceinline__ float sigf(float x){ return 1.f/(1.f+__expf(-x)); }

__device__ __forceinline__ void mma_tf32(float* d, const unsigned* a, const unsigned* b){
  asm volatile("mma.sync.aligned.m16n8k8.row.col.f32.tf32.tf32.f32 "
    "{%0,%1,%2,%3}, {%4,%5,%6,%7}, {%8,%9}, {%0,%1,%2,%3};\n"
    : "+f"(d[0]), "+f"(d[1]), "+f"(d[2]), "+f"(d[3])
    : "r"(a[0]), "r"(a[1]), "r"(a[2]), "r"(a[3]), "r"(b[0]), "r"(b[1]));
}

// ---------------- init: build concat weights, bias sums, zero states ----------------
__global__ void init_k(const float* __restrict__ eWih, const float* __restrict__ eWhh,
                       const float* __restrict__ dW1,  const float* __restrict__ dWhh,
                       const float* __restrict__ ebih, const float* __restrict__ ebhh,
                       const float* __restrict__ dbih, const float* __restrict__ dbhh){
  int i = blockIdx.x*blockDim.x + threadIdx.x;
  if (i < G4*768){
    int n = i/768, k = i%768;
    d_Wcat[i] = (k < DIN) ? eWih[n*DIN + k] : eWhh[n*HE + (k - DIN)];
  }
  if (i < NDEC*1024){
    int n = i >> 10, k = i & 1023;
    float v;
    if (n < 512)      v = dW1[n*1536 + k];
    else if (k < 512) v = dWhh[(n-512)*512 + k];
    else              v = 0.f;
    d_WdecB[i] = v;
  }
  if (i < G4) d_biasEnc[i] = ebih[i] + ebhh[i];
  if (i < NDEC) d_biasDec[i] = (i < 512) ? 0.f : (dbih[i-512] + dbhh[i-512]);
  if (i < BSZ*HE){
    d_xh[(i/HE)*768 + DIN + (i%HE)] = 0.f;
    d_c_enc[i] = 0.f;
  }
  if (i < BSZ*2*HD) d_hs[i] = 0.f;
}

// ---------------- t2[b,s,d] = sum_t X[b,t,d]*Wd[s,t] + bd[s] ----------------
__global__ void t2_k(const float* __restrict__ inp, const float* __restrict__ Wd,
                     const float* __restrict__ bd){
  int bs = blockIdx.x;              // b*31 + s
  int b = bs / TM1, s = bs % TM1;
  int d = threadIdx.x;              // 256 threads
  __shared__ float wd[TM1];
  if (d < TM1) wd[d] = Wd[s*TM1 + d];
  __syncthreads();
  float acc = bd[s];
  const float* xb = inp + (size_t)b*TM1*257 + 1 + d;
  #pragma unroll
  for (int t = 0; t < TM1; t++) acc += xb[t*257] * wd[t];
  d_t2[(size_t)bs*DIN + d] = acc;
}

// ---- encoder fused: LSTM pointwise for step t-1 (from split-K gates) + attention ----
__global__ void enc_fused_k(const float* __restrict__ inp, const float* __restrict__ Wc,
                            const float* __restrict__ bc, const float* __restrict__ Wa,
                            const float* __restrict__ ba, int t){
  int b = blockIdx.x, tid = threadIdx.x, lane = tid & 31, warp = tid >> 5;
  __shared__ float hsm[1024];       // [h | c]
  __shared__ float t1[TM1];
  __shared__ float red[8];
  if (t == 0){
    for (int i = tid; i < 1024; i += 256) hsm[i] = 0.f;
  } else {
    const float* g0 = d_gs + (size_t)b*G4;
    const float* g1 = d_gs + (size_t)BSZ*G4 + (size_t)b*G4;
    for (int u = tid; u < HE; u += 256){
      float gi = g0[u]      + g1[u];
      float gf = g0[u+512]  + g1[u+512];
      float gg = g0[u+1024] + g1[u+1024];
      float go = g0[u+1536] + g1[u+1536];
      float cold = d_c_enc[b*HE + u];
      float c2 = sigf(gf)*cold + sigf(gi)*tanhf(gg);
      float h2 = sigf(go)*tanhf(c2);
      hsm[u]      = h2;
      hsm[HE + u] = c2;
      d_c_enc[b*HE + u] = c2;
      d_xh[b*768 + DIN + u] = h2;
      d_enc_out[((size_t)b*TM1 + (t-1))*HE + u] = h2;
    }
  }
  __syncthreads();
  for (int s = warp; s < TM1; s += 8){
    const float* wr = Wc + s*1024;
    float acc = 0.f;
    for (int k = lane; k < 1024; k += 32) acc += hsm[k]*wr[k];
    #pragma unroll
    for (int o = 16; o; o >>= 1) acc += __shfl_xor_sync(0xffffffffu, acc, o);
    if (!lane) t1[s] = acc + bc[s];
  }
  __syncthreads();
  float sc = ba[0];
  const float* t2p = d_t2 + (size_t)b*TM1*DIN + tid;
  #pragma unroll
  for (int s = 0; s < TM1; s++) sc += tanhf(t1[s] + t2p[s*DIN]) * Wa[s];
  float v = sc;
  #pragma unroll
  for (int o = 16; o; o >>= 1) v = fmaxf(v, __shfl_xor_sync(0xffffffffu, v, o));
  if (!lane) red[warp] = v;
  __syncthreads();
  float m = red[0];
  #pragma unroll
  for (int w = 1; w < 8; w++) m = fmaxf(m, red[w]);
  float e = __expf(sc - m);
  __syncthreads();
  v = e;
  #pragma unroll
  for (int o = 16; o; o >>= 1) v += __shfl_xor_sync(0xffffffffu, v, o);
  if (!lane) red[warp] = v;
  __syncthreads();
  float sum = 0.f;
  #pragma unroll
  for (int w = 0; w < 8; w++) sum += red[w];
  float x = inp[((size_t)b*TM1 + t)*257 + 1 + tid];
  d_xh[b*768 + tid] = (e/sum) * x;
}

// ---------------- encoder tail: pointwise for t=30 -> enc_out ----------------
__global__ void enc_tail_k(){
  int i = blockIdx.x*blockDim.x + threadIdx.x;   // B*HE
  int b = i >> 9, u = i & 511;
  const float* g0 = d_gs + (size_t)b*G4;
  const float* g1 = d_gs + (size_t)BSZ*G4 + (size_t)b*G4;
  float gi = g0[u]      + g1[u];
  float gf = g0[u+512]  + g1[u+512];
  float gg = g0[u+1024] + g1[u+1024];
  float go = g0[u+1536] + g1[u+1536];
  float c  = d_c_enc[i];
  float c2 = sigf(gf)*c + sigf(gi)*tanhf(gg);
  float h2 = sigf(go)*tanhf(c2);
  d_enc_out[((size_t)b*TM1 + (TM1-1))*HE + u] = h2;
}

// ---------------- tf32 tensor-core GEMM: 64x64 tile, 128 threads, split-K ---------
// C[M,N] = A[M,K] @ B[N,K]^T (+bias[n]).  M,N mult 64, K mult 32.
// gridDim.z selects K-split: z=0 does K [0,Kz0) (adds bias), z=1 does [Kz0,Kz0+Kz1)
// but only for blockIdx.x < nsplit1 (other z=1 blocks exit). z writes to
// C + z*cStride; the consumer sums the halves.
// Register-prefetch + double-buffered smem, ONE __syncthreads per K-chunk.
// Raw fp32 bits fed to HMMA (tf32 truncation, no cvt).
#define GK 32
__global__ void __launch_bounds__(128) gemm_tc(int M, int N, int Kz0, int Kz1, int nsplit1,
    const float* __restrict__ A, int lda,
    const float* __restrict__ B, int ldb,
    float* __restrict__ C, int ldc, size_t cStride,
    const float* __restrict__ bias){
  int z = blockIdx.z;
  if (z == 1 && blockIdx.x >= nsplit1) return;
  int kBeg = z ? Kz0 : 0;
  int Krun = z ? Kz1 : Kz0;
  int KT = Krun >> 5;

  __shared__ __align__(16) float As[2][64][GK+4];   // stride 36, 2 stages
  __shared__ __align__(16) float Bs[2][64][GK+4];
  int tid = threadIdx.x, lane = tid & 31, warp = tid >> 5;
  int wm = warp >> 1, wn = warp & 1;
  int bm = blockIdx.y*64, bn = blockIdx.x*64;
  const float* Ab = A + (size_t)bm*lda + kBeg;
  const float* Bb = B + (size_t)bn*ldb + kBeg;
  C += (size_t)z*cStride;
  int r0 = tid >> 3, kc = (tid & 7) << 2;

  float4 ar[4], br[4];
  #pragma unroll
  for (int i = 0; i < 4; i++){
    int row = r0 + 16*i;
    ar[i] = *(const float4*)(Ab + (size_t)row*lda + kc);
    br[i] = *(const float4*)(Bb + (size_t)row*ldb + kc);
  }
  #pragma unroll
  for (int i = 0; i < 4; i++){
    int row = r0 + 16*i;
    *(float4*)&As[0][row][kc] = ar[i];
    *(float4*)&Bs[0][row][kc] = br[i];
  }
  __syncthreads();

  float acc[2][4][4] = {};
  int r = lane >> 2, c = lane & 3;

  for (int kt = 0; kt < KT; kt++){
    int cur = kt & 1;
    if (kt + 1 < KT){
      #pragma unroll
      for (int i = 0; i < 4; i++){
        int row = r0 + 16*i;
        ar[i] = *(const float4*)(Ab + (size_t)row*lda + (kt+1)*GK + kc);
        br[i] = *(const float4*)(Bb + (size_t)row*ldb + (kt+1)*GK + kc);
      }
    }
    #pragma unroll
    for (int kk = 0; kk < GK; kk += 8){
      unsigned af[2][4], bf[4][2];
      #pragma unroll
      for (int mt = 0; mt < 2; mt++){
        int m0 = wm*32 + mt*16;
        af[mt][0] = __float_as_uint(As[cur][m0 + r    ][kk + c    ]);
        af[mt][1] = __float_as_uint(As[cur][m0 + r + 8][kk + c    ]);
        af[mt][2] = __float_as_uint(As[cur][m0 + r    ][kk + c + 4]);
        af[mt][3] = __float_as_uint(As[cur][m0 + r + 8][kk + c + 4]);
      }
      #pragma unroll
      for (int nt = 0; nt < 4; nt++){
        int n0 = wn*32 + nt*8;
        bf[nt][0] = __float_as_uint(Bs[cur][n0 + r][kk + c    ]);
        bf[nt][1] = __float_as_uint(Bs[cur][n0 + r][kk + c + 4]);
      }
      #pragma unroll
      for (int mt = 0; mt < 2; mt++)
        #pragma unroll
        for (int nt = 0; nt < 4; nt++)
          mma_tf32(acc[mt][nt], af[mt], bf[nt]);
    }
    if (kt + 1 < KT){
      int nxt = cur ^ 1;
      #pragma unroll
      for (int i = 0; i < 4; i++){
        int row = r0 + 16*i;
        *(float4*)&As[nxt][row][kc] = ar[i];
        *(float4*)&Bs[nxt][row][kc] = br[i];
      }
      __syncthreads();
    }
  }

  const float* biasz = (z == 0) ? bias : nullptr;
  int c2 = (lane & 3) << 1;
  #pragma unroll
  for (int mt = 0; mt < 2; mt++){
    #pragma unroll
    for (int nt = 0; nt < 4; nt++){
      int row = bm + wm*32 + mt*16 + r;
      int col = bn + wn*32 + nt*8 + c2;
      float b0 = biasz ? biasz[col] : 0.f;
      float b1 = biasz ? biasz[col+1] : 0.f;
      float2 v0; v0.x = acc[mt][nt][0] + b0; v0.y = acc[mt][nt][1] + b1;
      float2 v1; v1.x = acc[mt][nt][2] + b0; v1.y = acc[mt][nt][3] + b1;
      *(float2*)&C[(size_t)row*ldc + col]       = v0;
      *(float2*)&C[(size_t)(row+8)*ldc + col]   = v1;
    }
  }
}

// ---------------- decoder attention + context + y_tilde + LSTM + (final) ----------
// hsW (cols 0..511) = buf0 + buf1 (split-K halves); gates (cols 512..) = buf0 only
// (Whh's K range lies entirely in split 0).
__global__ void dec_attn_k(const float* __restrict__ inp, const float* __restrict__ W2,
                           const float* __restrict__ b2, const float* __restrict__ fcW,
                           const float* __restrict__ fcb, const float* __restrict__ dWih,
                           const float* __restrict__ fcfW, const float* __restrict__ fcfb,
                           float* __restrict__ out, int t, int last){
  int b = blockIdx.x, tid = threadIdx.x, lane = tid & 31, warp = tid >> 5;
  __shared__ float sc[TM1];
  __shared__ float a_sh[TM1];
  __shared__ float red[16];
  __shared__ float s_yt, s_cd;
  const float* hw0 = d_db + (size_t)b*NDEC;
  const float* hw1 = d_db + (size_t)BSZ*NDEC + (size_t)b*NDEC;
  for (int s = warp; s < TM1; s += 8){
    const float* ew = d_encW + ((size_t)b*TM1 + s)*HE;
    float acc = 0.f;
    for (int e = lane; e < HE; e += 32) acc += tanhf(hw0[e] + hw1[e] + ew[e]) * W2[e];
    #pragma unroll
    for (int o = 16; o; o >>= 1) acc += __shfl_xor_sync(0xffffffffu, acc, o);
    if (!lane) sc[s] = acc + b2[0];
  }
  __syncthreads();
  float m = -1e30f;
  #pragma unroll
  for (int s = 0; s < TM1; s++) m = fmaxf(m, sc[s]);
  float sum = 0.f;
  #pragma unroll
  for (int s = 0; s < TM1; s++) sum += __expf(sc[s] - m);
  if (tid < TM1) a_sh[tid] = __expf(sc[tid] - m) / sum;
  __syncthreads();
  float part = 0.f, cpart = 0.f;
  for (int e = tid; e < HE; e += 256){
    const float* eo = d_enc_out + (size_t)b*TM1*HE + e;
    float acc = 0.f;
    #pragma unroll
    for (int s = 0; s < TM1; s++) acc += a_sh[s]*eo[s*HE];
    part += acc * fcW[e];
    if (last) cpart += acc * fcfW[HE + e];
  }
  #pragma unroll
  for (int o = 16; o; o >>= 1){
    part  += __shfl_xor_sync(0xffffffffu, part, o);
    cpart += __shfl_xor_sync(0xffffffffu, cpart, o);
  }
  if (!lane){ red[warp] = part; red[8+warp] = cpart; }
  __syncthreads();
  if (tid == 0){
    float tot = 0.f, ctot = 0.f;
    #pragma unroll
    for (int w = 0; w < 8; w++){ tot += red[w]; ctot += red[8+w]; }
    float yv = inp[((size_t)b*TM1 + t)*257];     // y_hist[b,t,0]
    s_yt = tot + yv*fcW[HE] + fcb[0];
    s_cd = ctot;
  }
  __syncthreads();
  float y = s_yt;
  float hpart = 0.f;
  const float* g = hw0 + 512;                    // gates (biases included, split 0 only)
  for (int u = tid; u < HE; u += 256){
    float gi = g[u]      + y*dWih[u];
    float gf = g[u+512]  + y*dWih[u+512];
    float gg = g[u+1024] + y*dWih[u+1024];
    float go = g[u+1536] + y*dWih[u+1536];
    float cold = d_hs[b*1024 + 512 + u];
    float c2 = sigf(gf)*cold + sigf(gi)*tanhf(gg);
    float h2 = sigf(go)*tanhf(c2);
    d_hs[b*1024 + u]       = h2;
    d_hs[b*1024 + 512 + u] = c2;
    if (last) hpart += h2 * fcfW[u];
  }
  if (last){
    #pragma unroll
    for (int o = 16; o; o >>= 1) hpart += __shfl_xor_sync(0xffffffffu, hpart, o);
    __syncthreads();
    if (!lane) red[warp] = hpart;
    __syncthreads();
    if (tid == 0){
      float tot = 0.f;
      #pragma unroll
      for (int w = 0; w < 8; w++) tot += red[w];
      out[b] = tot + s_cd + fcfb[0];
    }
  }
}

// ---------------- launch ----------------
extern "C" void kernel_launch(void* const* d_in, const int* in_sizes, int n_in,
                              void* d_out, int out_size){
  const float* inp     = (const float*)d_in[0];
  const float* eWih    = (const float*)d_in[1];
  const float* eWhh    = (const float*)d_in[2];
  const float* ebih    = (const float*)d_in[3];
  const float* ebhh    = (const float*)d_in[4];
  const float* eWc     = (const float*)d_in[5];
  const float* ebc     = (const float*)d_in[6];
  const float* eWd     = (const float*)d_in[7];
  const float* ebd     = (const float*)d_in[8];
  const float* eWa     = (const float*)d_in[9];
  const float* eba     = (const float*)d_in[10];
  const float* dW1     = (const float*)d_in[11];
  const float* db1     = (const float*)d_in[12];
  const float* dW2     = (const float*)d_in[13];
  const float* db2     = (const float*)d_in[14];
  const float* dWih    = (const float*)d_in[15];
  const float* dWhh    = (const float*)d_in[16];
  const float* dbih    = (const float*)d_in[17];
  const float* dbhh    = (const float*)d_in[18];
  const float* fcW     = (const float*)d_in[19];
  const float* fcb     = (const float*)d_in[20];
  const float* fcfW    = (const float*)d_in[21];
  const float* fcfb    = (const float*)d_in[22];
  float* out = (float*)d_out;

  float *p_xh, *p_gs, *p_Wcat, *p_enc_out, *p_encW, *p_hs, *p_db, *p_WdecB, *p_bE, *p_bD;
  cudaGetSymbolAddress((void**)&p_xh, d_xh);
  cudaGetSymbolAddress((void**)&p_gs, d_gs);
  cudaGetSymbolAddress((void**)&p_Wcat, d_Wcat);
  cudaGetSymbolAddress((void**)&p_enc_out, d_enc_out);
  cudaGetSymbolAddress((void**)&p_encW, d_encW);
  cudaGetSymbolAddress((void**)&p_hs, d_hs);
  cudaGetSymbolAddress((void**)&p_db, d_db);
  cudaGetSymbolAddress((void**)&p_WdecB, d_WdecB);
  cudaGetSymbolAddress((void**)&p_bE, d_biasEnc);
  cudaGetSymbolAddress((void**)&p_bD, d_biasDec);

  init_k<<<(NDEC*1024 + 255)/256, 256>>>(eWih, eWhh, dW1, dWhh, ebih, ebhh, dbih, dbhh);
  t2_k<<<BSZ*TM1, 256>>>(inp, eWd, ebd);

  dim3 gEnc(G4/64, BSZ/64, 2);           // 32 x 8 x 2 = 512 blocks, K split 384+384
  dim3 gEncW(HE/64, (BSZ*TM1)/64, 1);    // 8 x 248 = 1984 blocks
  dim3 gDec(NDEC/64, BSZ/64, 2);         // 40 x 8 x 2; z=1 active only for bx<8

  // -------- encoder scan: 2 kernels per step --------
  for (int t = 0; t < TM1; t++){
    enc_fused_k<<<BSZ, 256>>>(inp, eWc, ebc, eWa, eba, t);
    gemm_tc<<<gEnc, 128>>>(BSZ, G4, 384, 384, G4/64,
                           p_xh, 768, p_Wcat, 768, p_gs, G4, (size_t)BSZ*G4, p_bE);
  }
  enc_tail_k<<<BSZ*HE/256, 256>>>();

  // -------- hoisted: encW = enc_out @ W1[:,1024:].T + b1 --------
  gemm_tc<<<gEncW, 128>>>(BSZ*TM1, HE, HE, 0, 0,
                          p_enc_out, HE, dW1 + 1024, 1536, p_encW, HE, 0, db1);

  // -------- decoder scan: 2 kernels per step --------
  for (int t = 0; t < TM1; t++){
    gemm_tc<<<gDec, 128>>>(BSZ, NDEC, 512, 512, 8,
                           p_hs, 1024, p_WdecB, 1024, p_db, NDEC, (size_t)BSZ*NDEC, p_bD);
    dec_attn_k<<<BSZ, 256>>>(inp, dW2, db2, fcW, fcb, dWih, fcfW, fcfb,
                             out, t, t == TM1-1);
  }
}

// round 17
// speedup vs baseline: 1.9325x; 1.0534x over previous
#include <cuda_runtime.h>
#include <cstddef>

#define BSZ 512
#define TM1 31
#define DIN 256
#define HE 512
#define HD 512
#define G4 2048   // 4*HE
#define NDEC 2560 // 512 (hsW) + 2048 (lstm gates)

// ---------------- scratch (device globals; no allocation) ----------------
__device__ __align__(16) float d_t2[BSZ*TM1*DIN];       // (b, s, d)
__device__ __align__(16) float d_xh[BSZ*768];           // [w(256) | h(512)] per batch
__device__ __align__(16) float d_c_enc[BSZ*HE];
__device__ __align__(16) float d_gs[2*BSZ*G4];          // enc gates, split-K halves
__device__ __align__(16) float d_enc_out[(size_t)BSZ*TM1*HE];
__device__ __align__(16) float d_encW[(size_t)BSZ*TM1*HE];
__device__ __align__(16) float d_hs[BSZ*2*HD];          // decoder [h | c]
__device__ __align__(16) float d_db[2*BSZ*NDEC];        // dec [hsW|gates], split-K halves
__device__ __align__(16) float d_Wcat[G4*768];          // [enc_Wih | enc_Whh] row-concat
__device__ __align__(16) float d_WdecB[(size_t)NDEC*1024]; // [W1[:, :1024] ; Whh pad]
__device__ __align__(16) float d_biasEnc[G4];           // enc bih+bhh
__device__ __align__(16) float d_biasDec[NDEC];         // [0(512) | dec bih+bhh]

__device__ __forceinline__ float sigf(float x){ return 1.f/(1.f+__expf(-x)); }

// hardware tanh (MUFU) — used ONLY in softmax-score paths (error smoothed by softmax)
__device__ __forceinline__ float tanh_fast(float x){
  float y; asm("tanh.approx.f32 %0, %1;" : "=f"(y) : "f"(x)); return y;
}

__device__ __forceinline__ void mma_tf32(float* d, const unsigned* a, const unsigned* b){
  asm volatile("mma.sync.aligned.m16n8k8.row.col.f32.tf32.tf32.f32 "
    "{%0,%1,%2,%3}, {%4,%5,%6,%7}, {%8,%9}, {%0,%1,%2,%3};\n"
    : "+f"(d[0]), "+f"(d[1]), "+f"(d[2]), "+f"(d[3])
    : "r"(a[0]), "r"(a[1]), "r"(a[2]), "r"(a[3]), "r"(b[0]), "r"(b[1]));
}

// ---------------- init: build concat weights, bias sums, zero states ----------------
__global__ void init_k(const float* __restrict__ eWih, const float* __restrict__ eWhh,
                       const float* __restrict__ dW1,  const float* __restrict__ dWhh,
                       const float* __restrict__ ebih, const float* __restrict__ ebhh,
                       const float* __restrict__ dbih, const float* __restrict__ dbhh){
  int i = blockIdx.x*blockDim.x + threadIdx.x;
  if (i < G4*768){
    int n = i/768, k = i%768;
    d_Wcat[i] = (k < DIN) ? eWih[n*DIN + k] : eWhh[n*HE + (k - DIN)];
  }
  if (i < NDEC*1024){
    int n = i >> 10, k = i & 1023;
    float v;
    if (n < 512)      v = dW1[n*1536 + k];
    else if (k < 512) v = dWhh[(n-512)*512 + k];
    else              v = 0.f;
    d_WdecB[i] = v;
  }
  if (i < G4) d_biasEnc[i] = ebih[i] + ebhh[i];
  if (i < NDEC) d_biasDec[i] = (i < 512) ? 0.f : (dbih[i-512] + dbhh[i-512]);
  if (i < BSZ*HE){
    d_xh[(i/HE)*768 + DIN + (i%HE)] = 0.f;
    d_c_enc[i] = 0.f;
  }
  if (i < BSZ*2*HD) d_hs[i] = 0.f;
}

// ---------------- t2[b,s,d] = sum_t X[b,t,d]*Wd[s,t] + bd[s] ----------------
__global__ void t2_k(const float* __restrict__ inp, const float* __restrict__ Wd,
                     const float* __restrict__ bd){
  int bs = blockIdx.x;              // b*31 + s
  int b = bs / TM1, s = bs % TM1;
  int d = threadIdx.x;              // 256 threads
  __shared__ float wd[TM1];
  if (d < TM1) wd[d] = Wd[s*TM1 + d];
  __syncthreads();
  float acc = bd[s];
  const float* xb = inp + (size_t)b*TM1*257 + 1 + d;
  #pragma unroll
  for (int t = 0; t < TM1; t++) acc += xb[t*257] * wd[t];
  d_t2[(size_t)bs*DIN + d] = acc;
}

// ---- encoder fused: LSTM pointwise for step t-1 (from split-K gates) + attention ----
__global__ void enc_fused_k(const float* __restrict__ inp, const float* __restrict__ Wc,
                            const float* __restrict__ bc, const float* __restrict__ Wa,
                            const float* __restrict__ ba, int t){
  int b = blockIdx.x, tid = threadIdx.x, lane = tid & 31, warp = tid >> 5;
  __shared__ float hsm[1024];       // [h | c]
  __shared__ float t1[TM1];
  __shared__ float red[8];
  if (t == 0){
    for (int i = tid; i < 1024; i += 256) hsm[i] = 0.f;
  } else {
    const float* g0 = d_gs + (size_t)b*G4;
    const float* g1 = d_gs + (size_t)BSZ*G4 + (size_t)b*G4;
    for (int u = tid; u < HE; u += 256){
      float gi = g0[u]      + g1[u];
      float gf = g0[u+512]  + g1[u+512];
      float gg = g0[u+1024] + g1[u+1024];
      float go = g0[u+1536] + g1[u+1536];
      float cold = d_c_enc[b*HE + u];
      float c2 = sigf(gf)*cold + sigf(gi)*tanhf(gg);
      float h2 = sigf(go)*tanhf(c2);
      hsm[u]      = h2;
      hsm[HE + u] = c2;
      d_c_enc[b*HE + u] = c2;
      d_xh[b*768 + DIN + u] = h2;
      d_enc_out[((size_t)b*TM1 + (t-1))*HE + u] = h2;
    }
  }
  __syncthreads();
  for (int s = warp; s < TM1; s += 8){
    const float* wr = Wc + s*1024;
    float acc = 0.f;
    for (int k = lane; k < 1024; k += 32) acc += hsm[k]*wr[k];
    #pragma unroll
    for (int o = 16; o; o >>= 1) acc += __shfl_xor_sync(0xffffffffu, acc, o);
    if (!lane) t1[s] = acc + bc[s];
  }
  __syncthreads();
  float sc = ba[0];
  const float* t2p = d_t2 + (size_t)b*TM1*DIN + tid;
  #pragma unroll
  for (int s = 0; s < TM1; s++) sc += tanh_fast(t1[s] + t2p[s*DIN]) * Wa[s];
  float v = sc;
  #pragma unroll
  for (int o = 16; o; o >>= 1) v = fmaxf(v, __shfl_xor_sync(0xffffffffu, v, o));
  if (!lane) red[warp] = v;
  __syncthreads();
  float m = red[0];
  #pragma unroll
  for (int w = 1; w < 8; w++) m = fmaxf(m, red[w]);
  float e = __expf(sc - m);
  __syncthreads();
  v = e;
  #pragma unroll
  for (int o = 16; o; o >>= 1) v += __shfl_xor_sync(0xffffffffu, v, o);
  if (!lane) red[warp] = v;
  __syncthreads();
  float sum = 0.f;
  #pragma unroll
  for (int w = 0; w < 8; w++) sum += red[w];
  float x = inp[((size_t)b*TM1 + t)*257 + 1 + tid];
  d_xh[b*768 + tid] = (e/sum) * x;
}

// ---------------- encoder tail: pointwise for t=30 -> enc_out ----------------
__global__ void enc_tail_k(){
  int i = blockIdx.x*blockDim.x + threadIdx.x;   // B*HE
  int b = i >> 9, u = i & 511;
  const float* g0 = d_gs + (size_t)b*G4;
  const float* g1 = d_gs + (size_t)BSZ*G4 + (size_t)b*G4;
  float gi = g0[u]      + g1[u];
  float gf = g0[u+512]  + g1[u+512];
  float gg = g0[u+1024] + g1[u+1024];
  float go = g0[u+1536] + g1[u+1536];
  float c  = d_c_enc[i];
  float c2 = sigf(gf)*c + sigf(gi)*tanhf(gg);
  float h2 = sigf(go)*tanhf(c2);
  d_enc_out[((size_t)b*TM1 + (TM1-1))*HE + u] = h2;
}

// ---------------- tf32 tensor-core GEMM: 64x64 tile, 128 threads, split-K ---------
// C[M,N] = A[M,K] @ B[N,K]^T (+bias[n]).  M,N mult 64, K mult 32.
// gridDim.z selects K-split: z=0 does K [0,Kz0) (adds bias), z=1 does [Kz0,Kz0+Kz1)
// but only for blockIdx.x < nsplit1 (other z=1 blocks exit). z writes to
// C + z*cStride; the consumer sums the halves.
// Register-prefetch + double-buffered smem, ONE __syncthreads per K-chunk.
// Raw fp32 bits fed to HMMA (tf32 truncation, no cvt).
#define GK 32
__global__ void __launch_bounds__(128) gemm_tc(int M, int N, int Kz0, int Kz1, int nsplit1,
    const float* __restrict__ A, int lda,
    const float* __restrict__ B, int ldb,
    float* __restrict__ C, int ldc, size_t cStride,
    const float* __restrict__ bias){
  int z = blockIdx.z;
  if (z == 1 && blockIdx.x >= nsplit1) return;
  int kBeg = z ? Kz0 : 0;
  int Krun = z ? Kz1 : Kz0;
  int KT = Krun >> 5;

  __shared__ __align__(16) float As[2][64][GK+4];   // stride 36, 2 stages
  __shared__ __align__(16) float Bs[2][64][GK+4];
  int tid = threadIdx.x, lane = tid & 31, warp = tid >> 5;
  int wm = warp >> 1, wn = warp & 1;
  int bm = blockIdx.y*64, bn = blockIdx.x*64;
  const float* Ab = A + (size_t)bm*lda + kBeg;
  const float* Bb = B + (size_t)bn*ldb + kBeg;
  C += (size_t)z*cStride;
  int r0 = tid >> 3, kc = (tid & 7) << 2;

  float4 ar[4], br[4];
  #pragma unroll
  for (int i = 0; i < 4; i++){
    int row = r0 + 16*i;
    ar[i] = *(const float4*)(Ab + (size_t)row*lda + kc);
    br[i] = *(const float4*)(Bb + (size_t)row*ldb + kc);
  }
  #pragma unroll
  for (int i = 0; i < 4; i++){
    int row = r0 + 16*i;
    *(float4*)&As[0][row][kc] = ar[i];
    *(float4*)&Bs[0][row][kc] = br[i];
  }
  __syncthreads();

  float acc[2][4][4] = {};
  int r = lane >> 2, c = lane & 3;

  for (int kt = 0; kt < KT; kt++){
    int cur = kt & 1;
    if (kt + 1 < KT){
      #pragma unroll
      for (int i = 0; i < 4; i++){
        int row = r0 + 16*i;
        ar[i] = *(const float4*)(Ab + (size_t)row*lda + (kt+1)*GK + kc);
        br[i] = *(const float4*)(Bb + (size_t)row*ldb + (kt+1)*GK + kc);
      }
    }
    #pragma unroll
    for (int kk = 0; kk < GK; kk += 8){
      unsigned af[2][4], bf[4][2];
      #pragma unroll
      for (int mt = 0; mt < 2; mt++){
        int m0 = wm*32 + mt*16;
        af[mt][0] = __float_as_uint(As[cur][m0 + r    ][kk + c    ]);
        af[mt][1] = __float_as_uint(As[cur][m0 + r + 8][kk + c    ]);
        af[mt][2] = __float_as_uint(As[cur][m0 + r    ][kk + c + 4]);
        af[mt][3] = __float_as_uint(As[cur][m0 + r + 8][kk + c + 4]);
      }
      #pragma unroll
      for (int nt = 0; nt < 4; nt++){
        int n0 = wn*32 + nt*8;
        bf[nt][0] = __float_as_uint(Bs[cur][n0 + r][kk + c    ]);
        bf[nt][1] = __float_as_uint(Bs[cur][n0 + r][kk + c + 4]);
      }
      #pragma unroll
      for (int mt = 0; mt < 2; mt++)
        #pragma unroll
        for (int nt = 0; nt < 4; nt++)
          mma_tf32(acc[mt][nt], af[mt], bf[nt]);
    }
    if (kt + 1 < KT){
      int nxt = cur ^ 1;
      #pragma unroll
      for (int i = 0; i < 4; i++){
        int row = r0 + 16*i;
        *(float4*)&As[nxt][row][kc] = ar[i];
        *(float4*)&Bs[nxt][row][kc] = br[i];
      }
      __syncthreads();
    }
  }

  const float* biasz = (z == 0) ? bias : nullptr;
  int c2 = (lane & 3) << 1;
  #pragma unroll
  for (int mt = 0; mt < 2; mt++){
    #pragma unroll
    for (int nt = 0; nt < 4; nt++){
      int row = bm + wm*32 + mt*16 + r;
      int col = bn + wn*32 + nt*8 + c2;
      float b0 = biasz ? biasz[col] : 0.f;
      float b1 = biasz ? biasz[col+1] : 0.f;
      float2 v0; v0.x = acc[mt][nt][0] + b0; v0.y = acc[mt][nt][1] + b1;
      float2 v1; v1.x = acc[mt][nt][2] + b0; v1.y = acc[mt][nt][3] + b1;
      *(float2*)&C[(size_t)row*ldc + col]       = v0;
      *(float2*)&C[(size_t)(row+8)*ldc + col]   = v1;
    }
  }
}

// ---------------- decoder attention + context + y_tilde + LSTM + (final) ----------
// hsW (cols 0..511) = buf0 + buf1 (split-K halves); gates (cols 512..) = buf0 only
// (Whh's K range lies entirely in split 0).
__global__ void dec_attn_k(const float* __restrict__ inp, const float* __restrict__ W2,
                           const float* __restrict__ b2, const float* __restrict__ fcW,
                           const float* __restrict__ fcb, const float* __restrict__ dWih,
                           const float* __restrict__ fcfW, const float* __restrict__ fcfb,
                           float* __restrict__ out, int t, int last){
  int b = blockIdx.x, tid = threadIdx.x, lane = tid & 31, warp = tid >> 5;
  __shared__ float sc[TM1];
  __shared__ float a_sh[TM1];
  __shared__ float red[16];
  __shared__ float s_yt, s_cd;
  const float* hw0 = d_db + (size_t)b*NDEC;
  const float* hw1 = d_db + (size_t)BSZ*NDEC + (size_t)b*NDEC;
  for (int s = warp; s < TM1; s += 8){
    const float* ew = d_encW + ((size_t)b*TM1 + s)*HE;
    float acc = 0.f;
    for (int e = lane; e < HE; e += 32) acc += tanh_fast(hw0[e] + hw1[e] + ew[e]) * W2[e];
    #pragma unroll
    for (int o = 16; o; o >>= 1) acc += __shfl_xor_sync(0xffffffffu, acc, o);
    if (!lane) sc[s] = acc + b2[0];
  }
  __syncthreads();
  float m = -1e30f;
  #pragma unroll
  for (int s = 0; s < TM1; s++) m = fmaxf(m, sc[s]);
  float sum = 0.f;
  #pragma unroll
  for (int s = 0; s < TM1; s++) sum += __expf(sc[s] - m);
  if (tid < TM1) a_sh[tid] = __expf(sc[tid] - m) / sum;
  __syncthreads();
  float part = 0.f, cpart = 0.f;
  for (int e = tid; e < HE; e += 256){
    const float* eo = d_enc_out + (size_t)b*TM1*HE + e;
    float acc = 0.f;
    #pragma unroll
    for (int s = 0; s < TM1; s++) acc += a_sh[s]*eo[s*HE];
    part += acc * fcW[e];
    if (last) cpart += acc * fcfW[HE + e];
  }
  #pragma unroll
  for (int o = 16; o; o >>= 1){
    part  += __shfl_xor_sync(0xffffffffu, part, o);
    cpart += __shfl_xor_sync(0xffffffffu, cpart, o);
  }
  if (!lane){ red[warp] = part; red[8+warp] = cpart; }
  __syncthreads();
  if (tid == 0){
    float tot = 0.f, ctot = 0.f;
    #pragma unroll
    for (int w = 0; w < 8; w++){ tot += red[w]; ctot += red[8+w]; }
    float yv = inp[((size_t)b*TM1 + t)*257];     // y_hist[b,t,0]
    s_yt = tot + yv*fcW[HE] + fcb[0];
    s_cd = ctot;
  }
  __syncthreads();
  float y = s_yt;
  float hpart = 0.f;
  const float* g = hw0 + 512;                    // gates (biases included, split 0 only)
  for (int u = tid; u < HE; u += 256){
    float gi = g[u]      + y*dWih[u];
    float gf = g[u+512]  + y*dWih[u+512];
    float gg = g[u+1024] + y*dWih[u+1024];
    float go = g[u+1536] + y*dWih[u+1536];
    float cold = d_hs[b*1024 + 512 + u];
    float c2 = sigf(gf)*cold + sigf(gi)*tanhf(gg);
    float h2 = sigf(go)*tanhf(c2);
    d_hs[b*1024 + u]       = h2;
    d_hs[b*1024 + 512 + u] = c2;
    if (last) hpart += h2 * fcfW[u];
  }
  if (last){
    #pragma unroll
    for (int o = 16; o; o >>= 1) hpart += __shfl_xor_sync(0xffffffffu, hpart, o);
    __syncthreads();
    if (!lane) red[warp] = hpart;
    __syncthreads();
    if (tid == 0){
      float tot = 0.f;
      #pragma unroll
      for (int w = 0; w < 8; w++) tot += red[w];
      out[b] = tot + s_cd + fcfb[0];
    }
  }
}

// ---------------- launch ----------------
extern "C" void kernel_launch(void* const* d_in, const int* in_sizes, int n_in,
                              void* d_out, int out_size){
  const float* inp     = (const float*)d_in[0];
  const float* eWih    = (const float*)d_in[1];
  const float* eWhh    = (const float*)d_in[2];
  const float* ebih    = (const float*)d_in[3];
  const float* ebhh    = (const float*)d_in[4];
  const float* eWc     = (const float*)d_in[5];
  const float* ebc     = (const float*)d_in[6];
  const float* eWd     = (const float*)d_in[7];
  const float* ebd     = (const float*)d_in[8];
  const float* eWa     = (const float*)d_in[9];
  const float* eba     = (const float*)d_in[10];
  const float* dW1     = (const float*)d_in[11];
  const float* db1     = (const float*)d_in[12];
  const float* dW2     = (const float*)d_in[13];
  const float* db2     = (const float*)d_in[14];
  const float* dWih    = (const float*)d_in[15];
  const float* dWhh    = (const float*)d_in[16];
  const float* dbih    = (const float*)d_in[17];
  const float* dbhh    = (const float*)d_in[18];
  const float* fcW     = (const float*)d_in[19];
  const float* fcb     = (const float*)d_in[20];
  const float* fcfW    = (const float*)d_in[21];
  const float* fcfb    = (const float*)d_in[22];
  float* out = (float*)d_out;

  float *p_xh, *p_gs, *p_Wcat, *p_enc_out, *p_encW, *p_hs, *p_db, *p_WdecB, *p_bE, *p_bD;
  cudaGetSymbolAddress((void**)&p_xh, d_xh);
  cudaGetSymbolAddress((void**)&p_gs, d_gs);
  cudaGetSymbolAddress((void**)&p_Wcat, d_Wcat);
  cudaGetSymbolAddress((void**)&p_enc_out, d_enc_out);
  cudaGetSymbolAddress((void**)&p_encW, d_encW);
  cudaGetSymbolAddress((void**)&p_hs, d_hs);
  cudaGetSymbolAddress((void**)&p_db, d_db);
  cudaGetSymbolAddress((void**)&p_WdecB, d_WdecB);
  cudaGetSymbolAddress((void**)&p_bE, d_biasEnc);
  cudaGetSymbolAddress((void**)&p_bD, d_biasDec);

  init_k<<<(NDEC*1024 + 255)/256, 256>>>(eWih, eWhh, dW1, dWhh, ebih, ebhh, dbih, dbhh);
  t2_k<<<BSZ*TM1, 256>>>(inp, eWd, ebd);

  dim3 gEnc(G4/64, BSZ/64, 2);           // 32 x 8 x 2 = 512 blocks, K split 384+384
  dim3 gEncW(HE/64, (BSZ*TM1)/64, 1);    // 8 x 248 = 1984 blocks
  dim3 gDec(NDEC/64, BSZ/64, 2);         // 40 x 8 x 2; z=1 active only for bx<8

  // -------- encoder scan: 2 kernels per step --------
  for (int t = 0; t < TM1; t++){
    enc_fused_k<<<BSZ, 256>>>(inp, eWc, ebc, eWa, eba, t);
    gemm_tc<<<gEnc, 128>>>(BSZ, G4, 384, 384, G4/64,
                           p_xh, 768, p_Wcat, 768, p_gs, G4, (size_t)BSZ*G4, p_bE);
  }
  enc_tail_k<<<BSZ*HE/256, 256>>>();

  // -------- hoisted: encW = enc_out @ W1[:,1024:].T + b1 --------
  gemm_tc<<<gEncW, 128>>>(BSZ*TM1, HE, HE, 0, 0,
                          p_enc_out, HE, dW1 + 1024, 1536, p_encW, HE, 0, db1);

  // -------- decoder scan: 2 kernels per step --------
  for (int t = 0; t < TM1; t++){
    gemm_tc<<<gDec, 128>>>(BSZ, NDEC, 512, 512, 8,
                           p_hs, 1024, p_WdecB, 1024, p_db, NDEC, (size_t)BSZ*NDEC, p_bD);
    dec_attn_k<<<BSZ, 256>>>(inp, dW2, db2, fcW, fcb, dWih, fcfW, fcfb,
                             out, t, t == TM1-1);
  }
}